// round 13
// baseline (speedup 1.0000x reference)
#include <cuda_runtime.h>
#include <cuda_fp16.h>
#include <math.h>
#include <stdint.h>

// ---------------- problem constants ----------------
#define BATCHN  4
#define SEQLEN  2048
#define DMODEL  512
#define DINNER  1024
#define NHEADSN 16
#define HEADDIM 64
#define DSTATE  64
#define CONVDIM 1152
#define DINPROJ 2208
#define DFF     2048
#define NROWS   (BATCHN*SEQLEN)   // 8192
#define EPSV    1e-5f
#define NSEG    16
#define SEGL    128               // SEQLEN/NSEG

// ---------------- scratch ----------------
__device__ float  g_zx  [NROWS*DINPROJ];
__device__ float  g_xbc [NROWS*CONVDIM];
__device__ float  g_dec [8*SEQLEN*NHEADSN];
__device__ float  g_dts [8*SEQLEN*NHEADSN];
__device__ float  g_y   [8*SEQLEN*DINNER];
__device__ float  g_x2  [NROWS*DMODEL];
__device__ float  g_hf  [8*NHEADSN*NSEG*HEADDIM*DSTATE];
__device__ float  g_cd  [8*NHEADSN*SEQLEN];
__device__ __half g_h16 [NROWS*DMODEL];
__device__ __half g_yg16[NROWS*DINNER];
__device__ __half g_ff1h[NROWS*DFF];
__device__ __half g_wip [DINPROJ*DMODEL];
__device__ __half g_wop [DMODEL*DINNER];
__device__ __half g_w1  [DFF*DMODEL];
__device__ __half g_w2  [DMODEL*DFF];

// ---------------- helpers ----------------
__device__ __forceinline__ float geluf(float x) {
    return 0.5f * x * (1.0f + erff(x * 0.70710678118654752f));
}
__device__ __forceinline__ float siluf(float x) {
    return x / (1.0f + expf(-x));
}
__device__ __forceinline__ uint32_t sptr(const void* p) {
    return (uint32_t)__cvta_generic_to_shared(p);
}

#define CP16(dst, src) \
    asm volatile("cp.async.cg.shared.global [%0], [%1], 16;" :: "r"(dst), "l"(src))
#define CP16Z(dst, src, sz) \
    asm volatile("cp.async.cg.shared.global [%0], [%1], 16, %2;" :: "r"(dst), "l"(src), "r"(sz))
#define CP4(dst, src) \
    asm volatile("cp.async.ca.shared.global [%0], [%1], 4;" :: "r"(dst), "l"(src))
#define CP_COMMIT() asm volatile("cp.async.commit_group;")
#define CP_WAIT2()  asm volatile("cp.async.wait_group 2;")
#define CP_WAIT1()  asm volatile("cp.async.wait_group 1;")

__device__ __forceinline__ void ldsm4(uint32_t& q0, uint32_t& q1, uint32_t& q2, uint32_t& q3,
                                      uint32_t addr) {
    asm volatile("ldmatrix.sync.aligned.m8n8.x4.shared.b16 {%0,%1,%2,%3}, [%4];"
        : "=r"(q0), "=r"(q1), "=r"(q2), "=r"(q3) : "r"(addr));
}

// packed f32x2 helpers
__device__ __forceinline__ uint64_t pack2(float lo, float hi) {
    uint64_t r; asm("mov.b64 %0, {%1,%2};" : "=l"(r) : "f"(lo), "f"(hi)); return r;
}
__device__ __forceinline__ void unpack2(uint64_t v, float& lo, float& hi) {
    asm("mov.b64 {%0,%1}, %2;" : "=f"(lo), "=f"(hi) : "l"(v));
}
#define MUL2(d, a, b) \
    asm("mul.rn.f32x2 %0, %1, %2;" : "=l"(d) : "l"(a), "l"(b))
#define FMA2_SELF_MUL(h, d2, t1) \
    asm("fma.rn.f32x2 %0, %0, %1, %2;" : "+l"(h) : "l"(d2), "l"(t1))
#define FMA2_ACC(ys, h, c) \
    asm("fma.rn.f32x2 %0, %1, %2, %0;" : "+l"(ys) : "l"(h), "l"(c))

// ---------------- fused f32 -> f16 weight convert ----------------
__global__ void cvt_all_kernel(
    const float* __restrict__ s0, __half* __restrict__ d0, int n0,
    const float* __restrict__ s1, __half* __restrict__ d1, int n1,
    const float* __restrict__ s2, __half* __restrict__ d2, int n2,
    const float* __restrict__ s3, __half* __restrict__ d3, int n3)
{
    int i = (blockIdx.x*blockDim.x + threadIdx.x) << 2;
    const float* s; __half* d;
    if (i < n0)                    { s = s0;      d = d0; }
    else if (i < n0+n1)            { s = s1 - n0; d = d1 - n0; }
    else if (i < n0+n1+n2)         { s = s2 - (n0+n1); d = d2 - (n0+n1); }
    else if (i < n0+n1+n2+n3)      { s = s3 - (n0+n1+n2); d = d3 - (n0+n1+n2); }
    else return;
    float4 v = *(const float4*)&s[i];
    *(__half2*)&d[i]   = __floats2half2_rn(v.x, v.y);
    *(__half2*)&d[i+2] = __floats2half2_rn(v.z, v.w);
}

// ---------------- scan boundary zero ----------------
__global__ void zb_kernel(float* __restrict__ y)
{
    int s = blockIdx.x;
    int t0 = (s < 4) ? 0 : (SEQLEN - 1);
    float4* p = (float4*)(y + ((size_t)s*SEQLEN + t0)*DINNER);
    p[threadIdx.x] = make_float4(0.f, 0.f, 0.f, 0.f);
}

// ---------------- LayerNorm (D=512), fp16 output ----------------
__global__ void __launch_bounds__(128) ln_kernel(
    const float* __restrict__ x, const float* __restrict__ w,
    const float* __restrict__ b, __half* __restrict__ out)
{
    int row = blockIdx.x;
    int tid = threadIdx.x;
    const float4 v = ((const float4*)(x + (size_t)row*DMODEL))[tid];
    float s  = v.x + v.y + v.z + v.w;
    float ss = v.x*v.x + v.y*v.y + v.z*v.z + v.w*v.w;
    #pragma unroll
    for (int o = 16; o > 0; o >>= 1) {
        s  += __shfl_xor_sync(0xffffffffu, s,  o);
        ss += __shfl_xor_sync(0xffffffffu, ss, o);
    }
    __shared__ float as[4], ass[4];
    int wid = tid >> 5;
    if ((tid & 31) == 0) { as[wid] = s; ass[wid] = ss; }
    __syncthreads();
    s  = as[0] + as[1] + as[2] + as[3];
    ss = ass[0] + ass[1] + ass[2] + ass[3];
    float mean = s * (1.0f/DMODEL);
    float var  = ss * (1.0f/DMODEL) - mean*mean;
    float rstd = rsqrtf(var + EPSV);
    const float4 wv = ((const float4*)w)[tid];
    const float4 bv = ((const float4*)b)[tid];
    float o0 = (v.x - mean)*rstd*wv.x + bv.x;
    float o1 = (v.y - mean)*rstd*wv.y + bv.y;
    float o2 = (v.z - mean)*rstd*wv.z + bv.z;
    float o3 = (v.w - mean)*rstd*wv.w + bv.w;
    __half2* op = (__half2*)(out + (size_t)row*DMODEL + (tid << 2));
    op[0] = __floats2half2_rn(o0, o1);
    op[1] = __floats2half2_rn(o2, o3);
}

// ---------------- fp16 tensor-core GEMM (f32 accum) ----------------
#define NSTAGE  4
#define ROWB    80
#define OPSTAGE (128*ROWB)
#define SMBOFF  (NSTAGE*OPSTAGE)
#define GEMM_SMEM (2*NSTAGE*OPSTAGE)

template<int EPI, int OUTH>
__global__ void __launch_bounds__(512) gemm_h(
    const __half* __restrict__ A, const __half* __restrict__ W,
    const float* __restrict__ bias, const float* __restrict__ res,
    void* __restrict__ Cout, int M, int N, int K)
{
    extern __shared__ char smem[];
    const uint32_t su = (uint32_t)__cvta_generic_to_shared(smem);
    const int tid = threadIdx.x, lane = tid & 31, wid = tid >> 5;
    const int bm = blockIdx.y << 7, bn = blockIdx.x << 7;
    const int wm = (wid & 3)  << 5;
    const int wn = (wid >> 2) << 5;
    const int ntiles = K >> 5;

    const int lrow = tid >> 2;
    const int lcp  = tid & 3;
    const int an = bn + lrow;
    const uint32_t bsz = (an < N) ? 16u : 0u;
    const __half* aSrc = A + (size_t)(bm + lrow)*K + (lcp << 3);
    const __half* bSrc = W + (size_t)((an < N) ? an : 0)*K + (lcp << 3);
    const uint32_t dA = su + lrow*ROWB + (lcp << 4);
    const uint32_t dB = dA + SMBOFF;

    const int arow = ((lane >> 3) & 1)*8 + (lane & 7);
    const int abyt = (lane >> 4) << 4;
    uint32_t abase[2];
    #pragma unroll
    for (int i = 0; i < 2; i++)
        abase[i] = su + (wm + i*16 + arow)*ROWB + abyt;
    const int brow = (lane >> 4)*8 + (lane & 7);
    const int bbyt = ((lane >> 3) & 1) << 4;
    uint32_t bbase[2];
    #pragma unroll
    for (int j2 = 0; j2 < 2; j2++)
        bbase[j2] = su + SMBOFF + (wn + j2*16 + brow)*ROWB + bbyt;

    float acc[8][4];
    #pragma unroll
    for (int i = 0; i < 8; i++) { acc[i][0]=acc[i][1]=acc[i][2]=acc[i][3]=0.f; }

    auto issue_tile = [&](int tf) {
        const uint32_t so = (tf & (NSTAGE-1))*OPSTAGE;
        const int kh = tf << 5;
        CP16 (dA + so, aSrc + kh);
        CP16Z(dB + so, bSrc + kh, bsz);
    };

    issue_tile(0); CP_COMMIT();
    issue_tile(1); CP_COMMIT();
    issue_tile(2); CP_COMMIT();

    for (int t = 0; t < ntiles; t++) {
        CP_WAIT2();
        __syncthreads();
        if (t + 3 < ntiles) issue_tile(t + 3);
        CP_COMMIT();

        const uint32_t so = (t & (NSTAGE-1))*OPSTAGE;
        #pragma unroll
        for (int ks = 0; ks < 2; ks++) {
            const uint32_t ko = ks << 5;
            uint32_t af[2][4], bf[4][2];
            #pragma unroll
            for (int i = 0; i < 2; i++)
                ldsm4(af[i][0], af[i][1], af[i][2], af[i][3], abase[i] + so + ko);
            #pragma unroll
            for (int j2 = 0; j2 < 2; j2++) {
                uint32_t q0, q1, q2, q3;
                ldsm4(q0, q1, q2, q3, bbase[j2] + so + ko);
                bf[j2*2  ][0] = q0; bf[j2*2  ][1] = q1;
                bf[j2*2+1][0] = q2; bf[j2*2+1][1] = q3;
            }
            #pragma unroll
            for (int i = 0; i < 2; i++)
                #pragma unroll
                for (int j = 0; j < 4; j++) {
                    float* c = acc[i*4 + j];
                    asm volatile(
                        "mma.sync.aligned.m16n8k16.row.col.f32.f16.f16.f32 "
                        "{%0,%1,%2,%3}, {%4,%5,%6,%7}, {%8,%9}, {%0,%1,%2,%3};"
                        : "+f"(c[0]), "+f"(c[1]), "+f"(c[2]), "+f"(c[3])
                        : "r"(af[i][0]), "r"(af[i][1]), "r"(af[i][2]), "r"(af[i][3]),
                          "r"(bf[j][0]), "r"(bf[j][1]));
                }
        }
    }

    const int g = lane >> 2, tg = lane & 3;
    #pragma unroll
    for (int i = 0; i < 2; i++) {
        #pragma unroll
        for (int j = 0; j < 4; j++) {
            int row = bm + wm + i*16 + g;
            int col = bn + wn + j*8 + (tg << 1);
            if (col >= N) continue;
            float* c = acc[i*4 + j];
            float2 v0 = make_float2(c[0], c[1]);
            float2 v1 = make_float2(c[2], c[3]);
            if (EPI == 1 || EPI == 3) {
                float2 bv = *(const float2*)&bias[col];
                v0.x += bv.x; v0.y += bv.y;
                v1.x += bv.x; v1.y += bv.y;
            }
            if (EPI == 1) {
                v0.x = geluf(v0.x); v0.y = geluf(v0.y);
                v1.x = geluf(v1.x); v1.y = geluf(v1.y);
            }
            if (EPI == 2 || EPI == 3) {
                float2 r0 = *(const float2*)&res[(size_t)row*N + col];
                float2 r1 = *(const float2*)&res[(size_t)(row+8)*N + col];
                v0.x += r0.x; v0.y += r0.y;
                v1.x += r1.x; v1.y += r1.y;
            }
            if (OUTH) {
                __half* Ch = (__half*)Cout;
                *(__half2*)&Ch[(size_t)row*N + col]     = __floats2half2_rn(v0.x, v0.y);
                *(__half2*)&Ch[(size_t)(row+8)*N + col] = __floats2half2_rn(v1.x, v1.y);
            } else {
                float* Cf = (float*)Cout;
                *(float2*)&Cf[(size_t)row*N + col]     = v0;
                *(float2*)&Cf[(size_t)(row+8)*N + col] = v1;
            }
        }
    }
}

// ---------------- dt preprocess ----------------
__global__ void dt_kernel(const float* __restrict__ zx, const float* __restrict__ dt_bias,
                          const float* __restrict__ A_log,
                          float* __restrict__ dec, float* __restrict__ dts)
{
    int idx = blockIdx.x * blockDim.x + threadIdx.x;
    int hh = idx & 15;
    int t  = (idx >> 4) & (SEQLEN - 1);
    int s  = idx >> 15;
    int b  = s & 3;
    int off = (s < 4) ? 0 : NHEADSN;
    float raw = zx[((size_t)b*SEQLEN + t)*DINPROJ + (DINNER + CONVDIM) + off + hh] + dt_bias[hh];
    float sp = (raw > 20.f) ? raw : log1pf(expf(raw));
    float Ah = -expf(A_log[hh]);
    dec[idx] = expf(Ah * sp);
    dts[idx] = sp;
}

// ---------------- depthwise causal conv7 + bias + silu ----------------
__global__ void conv_kernel(const float* __restrict__ zx, const float* __restrict__ cw,
                            const float* __restrict__ cb, float* __restrict__ out)
{
    int idx = blockIdx.x * blockDim.x + threadIdx.x;
    int c  = (idx % (CONVDIM/4)) << 2;
    int bt = idx / (CONVDIM/4);
    int t  = bt & (SEQLEN - 1);
    int b  = bt >> 11;
    float4 acc = *(const float4*)&cb[c];
    float w[4][7];
    #pragma unroll
    for (int k = 0; k < 4; k++)
        #pragma unroll
        for (int j = 0; j < 7; j++) w[k][j] = cw[(c+k)*7 + j];
    const float* base = zx + (size_t)b*SEQLEN*DINPROJ + DINNER + c;
    #pragma unroll
    for (int j = 0; j < 7; j++) {
        int tt = t - 6 + j;
        if (tt >= 0) {
            float4 v = *(const float4*)&base[(size_t)tt*DINPROJ];
            acc.x = fmaf(v.x, w[0][j], acc.x);
            acc.y = fmaf(v.y, w[1][j], acc.y);
            acc.z = fmaf(v.z, w[2][j], acc.z);
            acc.w = fmaf(v.w, w[3][j], acc.w);
        }
    }
    float4 o;
    o.x = siluf(acc.x); o.y = siluf(acc.y);
    o.z = siluf(acc.z); o.w = siluf(acc.w);
    *(float4*)&out[((size_t)bt*CONVDIM) + c] = o;
}

// ---------------- segmented scan phase 1 (cp.async double-buffered) ----------------
__global__ void __launch_bounds__(256) scan_seg1(
    const float* __restrict__ xbc, const float* __restrict__ dec,
    const float* __restrict__ dts, float* __restrict__ y,
    float* __restrict__ hf, float* __restrict__ cd)
{
    const int h = blockIdx.x, s = blockIdx.y, k = blockIdx.z;
    const int b = s & 3;
    const bool fw = (s < 4);
    const int tid = threadIdx.x;
    const int p = tid >> 2;
    const int q = tid & 3;

    __shared__ float sX[2][16][64], sB[2][16][64], sC[2][16][64];
    __shared__ float sDec[2][16], sDt[2][16];

    uint64_t h2[8];
    #pragma unroll
    for (int i = 0; i < 8; i++) h2[i] = 0ull;
    float cdv = 1.f;

    const float* base = xbc + (size_t)b*SEQLEN*CONVDIM;
    float* yout = y + (size_t)s*SEQLEN*DINNER + h*HEADDIM + p;
    float* cdout = cd + ((size_t)s*NHEADSN + h)*SEQLEN;
    const int tau0 = k * SEGL;
    const int js = tid >> 4;            // 0..15
    const int n4 = (tid & 15) << 2;

    auto prefetch = [&](int cc, int buf) {
        int tau = tau0 + cc*16 + js;
        int orig = fw ? tau : (SEQLEN - 1 - tau);
        const float* row = base + (size_t)orig*CONVDIM;
        CP16(sptr(&sX[buf][js][n4]), &row[h*HEADDIM + n4]);
        CP16(sptr(&sB[buf][js][n4]), &row[DINNER + n4]);
        CP16(sptr(&sC[buf][js][n4]), &row[DINNER + DSTATE + n4]);
        if (tid < 32) {
            int t2 = tid & 15;
            int tau2 = tau0 + cc*16 + t2;
            int orig2 = fw ? tau2 : (SEQLEN - 1 - tau2);
            size_t di = ((size_t)s*SEQLEN + orig2)*NHEADSN + h;
            if (tid < 16) CP4(sptr(&sDec[buf][t2]), &dec[di]);
            else          CP4(sptr(&sDt[buf][t2]),  &dts[di]);
        }
    };

    const int nch = SEGL/16;            // 8
    prefetch(0, 0); CP_COMMIT();

    for (int cc = 0; cc < nch; cc++) {
        if (cc + 1 < nch) prefetch(cc + 1, (cc + 1) & 1);
        CP_COMMIT();
        CP_WAIT1();
        __syncthreads();
        const int bf = cc & 1;

        #pragma unroll 4
        for (int j = 0; j < 16; j++) {
            float d   = sDec[bf][j];
            float dtx = sDt[bf][j] * sX[bf][j][p];
            cdv *= d;
            uint64_t d2   = pack2(d, d);
            uint64_t dtx2 = pack2(dtx, dtx);
            uint64_t ys0  = 0ull, ys1 = 0ull;
            const longlong2* B4 = (const longlong2*)&sB[bf][j][q << 4];
            const longlong2* C4 = (const longlong2*)&sC[bf][j][q << 4];
            #pragma unroll
            for (int v = 0; v < 4; v++) {
                longlong2 bb = B4[v], cv = C4[v];
                uint64_t t1;
                MUL2(t1, dtx2, (uint64_t)bb.x);
                FMA2_SELF_MUL(h2[2*v], d2, t1);
                FMA2_ACC(ys0, h2[2*v], (uint64_t)cv.x);
                MUL2(t1, dtx2, (uint64_t)bb.y);
                FMA2_SELF_MUL(h2[2*v+1], d2, t1);
                FMA2_ACC(ys1, h2[2*v+1], (uint64_t)cv.y);
            }
            float a0, a1, b0, b1;
            unpack2(ys0, a0, a1);
            unpack2(ys1, b0, b1);
            float ysum = (a0 + a1) + (b0 + b1);
            ysum += __shfl_xor_sync(0xffffffffu, ysum, 1);
            ysum += __shfl_xor_sync(0xffffffffu, ysum, 2);
            int tau = tau0 + cc*16 + j;
            if (tid == 0) cdout[tau] = cdv;
            if (q == 0) {
                int to = fw ? (tau + 1) : (SEQLEN - 2 - tau);
                if (to >= 0 && to < SEQLEN)
                    yout[(size_t)to*DINNER] = ysum;
            }
        }
        __syncthreads();
    }

    uint64_t* hfp = (uint64_t*)(hf +
        ((((size_t)s*NHEADSN + h)*NSEG + k)*HEADDIM*DSTATE) + p*DSTATE + (q << 4));
    #pragma unroll
    for (int v = 0; v < 8; v++) hfp[v] = h2[v];
}

// ---------------- segmented scan phase 3 (cp.async double-buffered) ----------------
__global__ void __launch_bounds__(256) scan_seg3(
    const float* __restrict__ xbc, const float* __restrict__ cd,
    const float* __restrict__ hf, float* __restrict__ y)
{
    const int h = blockIdx.x, s = blockIdx.y, k = blockIdx.z + 1;
    const int b = s & 3;
    const bool fw = (s < 4);
    const int tid = threadIdx.x;
    const int p = tid >> 2;
    const int q = tid & 3;

    __shared__ float sC[2][16][64];
    __shared__ float sCd[2][16];

    const float* cdb = cd + ((size_t)s*NHEADSN + h)*SEQLEN;
    const float* cbase = xbc + (size_t)b*SEQLEN*CONVDIM + DINNER + DSTATE;
    float* yout = y + (size_t)s*SEQLEN*DINNER + h*HEADDIM + p;
    const int tau0 = k * SEGL;
    const int js = tid >> 4;
    const int n4 = (tid & 15) << 2;

    auto prefetch = [&](int cc, int buf) {
        int tau = tau0 + cc*16 + js;
        int orig = fw ? tau : (SEQLEN - 1 - tau);
        CP16(sptr(&sC[buf][js][n4]), &cbase[(size_t)orig*CONVDIM + n4]);
        if (tid < 16)
            CP4(sptr(&sCd[buf][tid]), &cdb[tau0 + cc*16 + tid]);
    };

    prefetch(0, 0); CP_COMMIT();

    // combine incoming state (overlaps with prefetch)
    uint64_t H[8];
    #pragma unroll
    for (int v = 0; v < 8; v++) H[v] = 0ull;
    for (int j = 0; j < k; j++) {
        float Pj = cdb[j*SEGL + SEGL - 1];
        uint64_t P2 = pack2(Pj, Pj);
        const uint64_t* hfp = (const uint64_t*)(hf +
            ((((size_t)s*NHEADSN + h)*NSEG + j)*HEADDIM*DSTATE) + p*DSTATE + (q << 4));
        #pragma unroll
        for (int v = 0; v < 8; v++) {
            uint64_t hv = hfp[v];
            FMA2_SELF_MUL(H[v], P2, hv);
        }
    }

    const int nch = SEGL/16;
    for (int cc = 0; cc < nch; cc++) {
        if (cc + 1 < nch) prefetch(cc + 1, (cc + 1) & 1);
        CP_COMMIT();
        CP_WAIT1();
        __syncthreads();
        const int bf = cc & 1;

        #pragma unroll 4
        for (int j = 0; j < 16; j++) {
            uint64_t ys0 = 0ull, ys1 = 0ull;
            const longlong2* C4 = (const longlong2*)&sC[bf][j][q << 4];
            #pragma unroll
            for (int v = 0; v < 4; v++) {
                longlong2 cv = C4[v];
                FMA2_ACC(ys0, H[2*v],   (uint64_t)cv.x);
                FMA2_ACC(ys1, H[2*v+1], (uint64_t)cv.y);
            }
            float a0, a1, b0, b1;
            unpack2(ys0, a0, a1);
            unpack2(ys1, b0, b1);
            float ysum = (a0 + a1) + (b0 + b1);
            ysum += __shfl_xor_sync(0xffffffffu, ysum, 1);
            ysum += __shfl_xor_sync(0xffffffffu, ysum, 2);
            if (q == 0) {
                int tau = tau0 + cc*16 + j;
                int to = fw ? (tau + 1) : (SEQLEN - 2 - tau);
                if (to >= 0 && to < SEQLEN) {
                    float* yp = &yout[(size_t)to*DINNER];
                    *yp = *yp + sCd[bf][j]*ysum;
                }
            }
        }
        __syncthreads();
    }
}

// ---------------- gating + D skip + RMS norm (fp16 output) ----------------
__global__ void __launch_bounds__(256) gate_rms_kernel(
    const float* __restrict__ y, const float* __restrict__ xbc,
    const float* __restrict__ zx, const float* __restrict__ Dp,
    const float* __restrict__ rms_w, __half* __restrict__ out)
{
    int row = blockIdx.x;
    int b = row >> 11, t = row & 2047;
    int c = threadIdx.x << 2;
    size_t ybase = ((size_t)b*SEQLEN + t)*DINNER + c;
    const float4 yf = *(const float4*)&y[ybase];
    const float4 yb = *(const float4*)&y[ybase + (size_t)4*SEQLEN*DINNER];
    const float4 xo = *(const float4*)&xbc[((size_t)b*SEQLEN + t)*CONVDIM + c];
    const float4 zv = *(const float4*)&zx[((size_t)b*SEQLEN + t)*DINPROJ + c];
    float dp = Dp[c >> 6];
    float g0 = (yf.x + yb.x + xo.x*dp) * siluf(zv.x);
    float g1 = (yf.y + yb.y + xo.y*dp) * siluf(zv.y);
    float g2 = (yf.z + yb.z + xo.z*dp) * siluf(zv.z);
    float g3 = (yf.w + yb.w + xo.w*dp) * siluf(zv.w);
    float ss = g0*g0 + g1*g1 + g2*g2 + g3*g3;
    #pragma unroll
    for (int o = 16; o > 0; o >>= 1)
        ss += __shfl_xor_sync(0xffffffffu, ss, o);
    __shared__ float asum[8];
    int wid = threadIdx.x >> 5;
    if ((threadIdx.x & 31) == 0) asum[wid] = ss;
    __syncthreads();
    ss = asum[0]+asum[1]+asum[2]+asum[3]+asum[4]+asum[5]+asum[6]+asum[7];
    float scale = rsqrtf(ss * (1.0f/DINNER) + EPSV);
    const float4 wv = *(const float4*)&rms_w[c];
    __half2* op = (__half2*)(out + (size_t)row*DINNER + c);
    op[0] = __floats2half2_rn(g0*scale*wv.x, g1*scale*wv.y);
    op[1] = __floats2half2_rn(g2*scale*wv.z, g3*scale*wv.w);
}

// ---------------- launcher ----------------
extern "C" void kernel_launch(void* const* d_in, const int* in_sizes, int n_in,
                              void* d_out, int out_size)
{
    const float* x         = (const float*)d_in[0];
    const float* ln1_w     = (const float*)d_in[1];
    const float* ln1_b     = (const float*)d_in[2];
    const float* in_proj_w = (const float*)d_in[3];
    const float* conv_w    = (const float*)d_in[4];
    const float* conv_b    = (const float*)d_in[5];
    const float* dt_bias   = (const float*)d_in[6];
    const float* A_log     = (const float*)d_in[7];
    const float* Dp        = (const float*)d_in[8];
    const float* rms_w     = (const float*)d_in[9];
    const float* out_proj_w= (const float*)d_in[10];
    const float* ln2_w     = (const float*)d_in[11];
    const float* ln2_b     = (const float*)d_in[12];
    const float* fc1_w     = (const float*)d_in[13];
    const float* fc1_b     = (const float*)d_in[14];
    const float* fc2_w     = (const float*)d_in[15];
    const float* fc2_b     = (const float*)d_in[16];
    float* out = (float*)d_out;

    float *zx, *xbc, *dec, *dts, *y, *x2, *hf, *cdp;
    __half *h16, *yg16, *ff1h, *wip, *wop, *w1, *w2;
    cudaGetSymbolAddress((void**)&zx,  g_zx);
    cudaGetSymbolAddress((void**)&xbc, g_xbc);
    cudaGetSymbolAddress((void**)&dec, g_dec);
    cudaGetSymbolAddress((void**)&dts, g_dts);
    cudaGetSymbolAddress((void**)&y,   g_y);
    cudaGetSymbolAddress((void**)&x2,  g_x2);
    cudaGetSymbolAddress((void**)&hf,  g_hf);
    cudaGetSymbolAddress((void**)&cdp, g_cd);
    cudaGetSymbolAddress((void**)&h16, g_h16);
    cudaGetSymbolAddress((void**)&yg16,g_yg16);
    cudaGetSymbolAddress((void**)&ff1h,g_ff1h);
    cudaGetSymbolAddress((void**)&wip, g_wip);
    cudaGetSymbolAddress((void**)&wop, g_wop);
    cudaGetSymbolAddress((void**)&w1,  g_w1);
    cudaGetSymbolAddress((void**)&w2,  g_w2);

    cudaFuncSetAttribute(gemm_h<0,0>, cudaFuncAttributeMaxDynamicSharedMemorySize, GEMM_SMEM);
    cudaFuncSetAttribute(gemm_h<1,1>, cudaFuncAttributeMaxDynamicSharedMemorySize, GEMM_SMEM);
    cudaFuncSetAttribute(gemm_h<2,0>, cudaFuncAttributeMaxDynamicSharedMemorySize, GEMM_SMEM);
    cudaFuncSetAttribute(gemm_h<3,0>, cudaFuncAttributeMaxDynamicSharedMemorySize, GEMM_SMEM);

    // 0. fused weight conversion
    {
        int n0 = DINPROJ*DMODEL, n1 = DMODEL*DINNER, n2 = DFF*DMODEL, n3 = DMODEL*DFF;
        int total4 = (n0+n1+n2+n3) >> 2;
        cvt_all_kernel<<<(total4 + 255)/256, 256>>>(
            in_proj_w, wip, n0, out_proj_w, wop, n1, fc1_w, w1, n2, fc2_w, w2, n3);
    }
    // 1. LN1
    ln_kernel<<<NROWS, 128>>>(x, ln1_w, ln1_b, h16);
    // 2. scan boundary zero
    zb_kernel<<<8, 256>>>(y);
    // 3. in_proj (launch #4 — profiled)
    gemm_h<0,0><<<dim3((DINPROJ + 127)/128, NROWS/128), 512, GEMM_SMEM>>>(
        h16, wip, nullptr, nullptr, zx, NROWS, DINPROJ, DMODEL);
    // 4. dt preprocess
    dt_kernel<<<(8*SEQLEN*NHEADSN)/256, 256>>>(zx, dt_bias, A_log, dec, dts);
    // 5. conv + silu
    conv_kernel<<<(NROWS*CONVDIM/4)/256, 256>>>(zx, conv_w, conv_b, xbc);
    // 6. segmented scan: local scans (2048 blocks)
    scan_seg1<<<dim3(NHEADSN, 8, NSEG), 256>>>(xbc, dec, dts, y, hf, cdp);
    // 7. segmented scan: cross-segment fixup (1920 blocks)
    scan_seg3<<<dim3(NHEADSN, 8, NSEG-1), 256>>>(xbc, cdp, hf, y);
    // 8. gate + D skip + RMS norm
    gate_rms_kernel<<<NROWS, 256>>>(y, xbc, zx, Dp, rms_w, yg16);
    // 9. out_proj + residual(x)
    gemm_h<2,0><<<dim3(DMODEL/128, NROWS/128), 512, GEMM_SMEM>>>(
        yg16, wop, nullptr, x, x2, NROWS, DMODEL, DINNER);
    // 10. LN2
    ln_kernel<<<NROWS, 128>>>(x2, ln2_w, ln2_b, h16);
    // 11. fc1 + bias + gelu
    gemm_h<1,1><<<dim3(DFF/128, NROWS/128), 512, GEMM_SMEM>>>(
        h16, w1, fc1_b, nullptr, ff1h, NROWS, DFF, DMODEL);
    // 12. fc2 + bias + residual(x2) -> d_out
    gemm_h<3,0><<<dim3(DMODEL/128, NROWS/128), 512, GEMM_SMEM>>>(
        ff1h, w2, fc2_b, x2, out, NROWS, DMODEL, DFF);
}

// round 14
// speedup vs baseline: 1.0770x; 1.0770x over previous
#include <cuda_runtime.h>
#include <cuda_fp16.h>
#include <math.h>
#include <stdint.h>

// ---------------- problem constants ----------------
#define BATCHN  4
#define SEQLEN  2048
#define DMODEL  512
#define DINNER  1024
#define NHEADSN 16
#define HEADDIM 64
#define DSTATE  64
#define CONVDIM 1152
#define DINPROJ 2208
#define DFF     2048
#define NROWS   (BATCHN*SEQLEN)   // 8192
#define EPSV    1e-5f
#define NSEG    8
#define SEGL    256               // SEQLEN/NSEG

// ---------------- scratch ----------------
__device__ float  g_zx  [NROWS*DINPROJ];
__device__ float  g_xbc [NROWS*CONVDIM];
__device__ float  g_dec [8*SEQLEN*NHEADSN];
__device__ float  g_dts [8*SEQLEN*NHEADSN];
__device__ float  g_y   [8*SEQLEN*DINNER];
__device__ float  g_x2  [NROWS*DMODEL];
__device__ float  g_hf  [8*NHEADSN*NSEG*HEADDIM*DSTATE];
__device__ float  g_cd  [8*NHEADSN*SEQLEN];
__device__ __half g_h16 [NROWS*DMODEL];
__device__ __half g_yg16[NROWS*DINNER];
__device__ __half g_ff1h[NROWS*DFF];
__device__ __half g_wip [DINPROJ*DMODEL];
__device__ __half g_wop [DMODEL*DINNER];
__device__ __half g_w1  [DFF*DMODEL];
__device__ __half g_w2  [DMODEL*DFF];

// ---------------- helpers ----------------
__device__ __forceinline__ float geluf(float x) {
    return 0.5f * x * (1.0f + erff(x * 0.70710678118654752f));
}
__device__ __forceinline__ float siluf(float x) {
    return x / (1.0f + expf(-x));
}

#define CP16(dst, src) \
    asm volatile("cp.async.cg.shared.global [%0], [%1], 16;" :: "r"(dst), "l"(src))
#define CP16Z(dst, src, sz) \
    asm volatile("cp.async.cg.shared.global [%0], [%1], 16, %2;" :: "r"(dst), "l"(src), "r"(sz))
#define CP_COMMIT() asm volatile("cp.async.commit_group;")
#define CP_WAIT2()  asm volatile("cp.async.wait_group 2;")

__device__ __forceinline__ void ldsm4(uint32_t& q0, uint32_t& q1, uint32_t& q2, uint32_t& q3,
                                      uint32_t addr) {
    asm volatile("ldmatrix.sync.aligned.m8n8.x4.shared.b16 {%0,%1,%2,%3}, [%4];"
        : "=r"(q0), "=r"(q1), "=r"(q2), "=r"(q3) : "r"(addr));
}

// packed f32x2 helpers
__device__ __forceinline__ uint64_t pack2(float lo, float hi) {
    uint64_t r; asm("mov.b64 %0, {%1,%2};" : "=l"(r) : "f"(lo), "f"(hi)); return r;
}
__device__ __forceinline__ void unpack2(uint64_t v, float& lo, float& hi) {
    asm("mov.b64 {%0,%1}, %2;" : "=f"(lo), "=f"(hi) : "l"(v));
}
#define MUL2(d, a, b) \
    asm("mul.rn.f32x2 %0, %1, %2;" : "=l"(d) : "l"(a), "l"(b))
#define FMA2_SELF_MUL(h, d2, t1) \
    asm("fma.rn.f32x2 %0, %0, %1, %2;" : "+l"(h) : "l"(d2), "l"(t1))
#define FMA2_ACC(ys, h, c) \
    asm("fma.rn.f32x2 %0, %1, %2, %0;" : "+l"(ys) : "l"(h), "l"(c))

// ---------------- fused f32 -> f16 weight convert ----------------
__global__ void cvt_all_kernel(
    const float* __restrict__ s0, __half* __restrict__ d0, int n0,
    const float* __restrict__ s1, __half* __restrict__ d1, int n1,
    const float* __restrict__ s2, __half* __restrict__ d2, int n2,
    const float* __restrict__ s3, __half* __restrict__ d3, int n3)
{
    int i = (blockIdx.x*blockDim.x + threadIdx.x) << 2;
    const float* s; __half* d;
    if (i < n0)                    { s = s0;      d = d0; }
    else if (i < n0+n1)            { s = s1 - n0; d = d1 - n0; }
    else if (i < n0+n1+n2)         { s = s2 - (n0+n1); d = d2 - (n0+n1); }
    else if (i < n0+n1+n2+n3)      { s = s3 - (n0+n1+n2); d = d3 - (n0+n1+n2); }
    else return;
    float4 v = *(const float4*)&s[i];
    *(__half2*)&d[i]   = __floats2half2_rn(v.x, v.y);
    *(__half2*)&d[i+2] = __floats2half2_rn(v.z, v.w);
}

// ---------------- scan boundary zero ----------------
__global__ void zb_kernel(float* __restrict__ y)
{
    int s = blockIdx.x;
    int t0 = (s < 4) ? 0 : (SEQLEN - 1);
    float4* p = (float4*)(y + ((size_t)s*SEQLEN + t0)*DINNER);
    p[threadIdx.x] = make_float4(0.f, 0.f, 0.f, 0.f);
}

// ---------------- LayerNorm (D=512), fp16 output ----------------
__global__ void __launch_bounds__(128) ln_kernel(
    const float* __restrict__ x, const float* __restrict__ w,
    const float* __restrict__ b, __half* __restrict__ out)
{
    int row = blockIdx.x;
    int tid = threadIdx.x;
    const float4 v = ((const float4*)(x + (size_t)row*DMODEL))[tid];
    float s  = v.x + v.y + v.z + v.w;
    float ss = v.x*v.x + v.y*v.y + v.z*v.z + v.w*v.w;
    #pragma unroll
    for (int o = 16; o > 0; o >>= 1) {
        s  += __shfl_xor_sync(0xffffffffu, s,  o);
        ss += __shfl_xor_sync(0xffffffffu, ss, o);
    }
    __shared__ float as[4], ass[4];
    int wid = tid >> 5;
    if ((tid & 31) == 0) { as[wid] = s; ass[wid] = ss; }
    __syncthreads();
    s  = as[0] + as[1] + as[2] + as[3];
    ss = ass[0] + ass[1] + ass[2] + ass[3];
    float mean = s * (1.0f/DMODEL);
    float var  = ss * (1.0f/DMODEL) - mean*mean;
    float rstd = rsqrtf(var + EPSV);
    const float4 wv = ((const float4*)w)[tid];
    const float4 bv = ((const float4*)b)[tid];
    float o0 = (v.x - mean)*rstd*wv.x + bv.x;
    float o1 = (v.y - mean)*rstd*wv.y + bv.y;
    float o2 = (v.z - mean)*rstd*wv.z + bv.z;
    float o3 = (v.w - mean)*rstd*wv.w + bv.w;
    __half2* op = (__half2*)(out + (size_t)row*DMODEL + (tid << 2));
    op[0] = __floats2half2_rn(o0, o1);
    op[1] = __floats2half2_rn(o2, o3);
}

// ---------------- fp16 tensor-core GEMM (f32 accum) ----------------
#define NSTAGE  4
#define ROWB    80
#define OPSTAGE (128*ROWB)
#define SMBOFF  (NSTAGE*OPSTAGE)
#define GEMM_SMEM (2*NSTAGE*OPSTAGE)

template<int EPI, int OUTH>
__global__ void __launch_bounds__(512) gemm_h(
    const __half* __restrict__ A, const __half* __restrict__ W,
    const float* __restrict__ bias, const float* __restrict__ res,
    void* __restrict__ Cout, int M, int N, int K)
{
    extern __shared__ char smem[];
    const uint32_t su = (uint32_t)__cvta_generic_to_shared(smem);
    const int tid = threadIdx.x, lane = tid & 31, wid = tid >> 5;
    const int bm = blockIdx.y << 7, bn = blockIdx.x << 7;
    const int wm = (wid & 3)  << 5;
    const int wn = (wid >> 2) << 5;
    const int ntiles = K >> 5;

    const int lrow = tid >> 2;
    const int lcp  = tid & 3;
    const int an = bn + lrow;
    const uint32_t bsz = (an < N) ? 16u : 0u;
    const __half* aSrc = A + (size_t)(bm + lrow)*K + (lcp << 3);
    const __half* bSrc = W + (size_t)((an < N) ? an : 0)*K + (lcp << 3);
    const uint32_t dA = su + lrow*ROWB + (lcp << 4);
    const uint32_t dB = dA + SMBOFF;

    const int arow = ((lane >> 3) & 1)*8 + (lane & 7);
    const int abyt = (lane >> 4) << 4;
    uint32_t abase[2];
    #pragma unroll
    for (int i = 0; i < 2; i++)
        abase[i] = su + (wm + i*16 + arow)*ROWB + abyt;
    const int brow = (lane >> 4)*8 + (lane & 7);
    const int bbyt = ((lane >> 3) & 1) << 4;
    uint32_t bbase[2];
    #pragma unroll
    for (int j2 = 0; j2 < 2; j2++)
        bbase[j2] = su + SMBOFF + (wn + j2*16 + brow)*ROWB + bbyt;

    float acc[8][4];
    #pragma unroll
    for (int i = 0; i < 8; i++) { acc[i][0]=acc[i][1]=acc[i][2]=acc[i][3]=0.f; }

    auto issue_tile = [&](int tf) {
        const uint32_t so = (tf & (NSTAGE-1))*OPSTAGE;
        const int kh = tf << 5;
        CP16 (dA + so, aSrc + kh);
        CP16Z(dB + so, bSrc + kh, bsz);
    };

    issue_tile(0); CP_COMMIT();
    issue_tile(1); CP_COMMIT();
    issue_tile(2); CP_COMMIT();

    for (int t = 0; t < ntiles; t++) {
        CP_WAIT2();
        __syncthreads();
        if (t + 3 < ntiles) issue_tile(t + 3);
        CP_COMMIT();

        const uint32_t so = (t & (NSTAGE-1))*OPSTAGE;
        #pragma unroll
        for (int ks = 0; ks < 2; ks++) {
            const uint32_t ko = ks << 5;
            uint32_t af[2][4], bf[4][2];
            #pragma unroll
            for (int i = 0; i < 2; i++)
                ldsm4(af[i][0], af[i][1], af[i][2], af[i][3], abase[i] + so + ko);
            #pragma unroll
            for (int j2 = 0; j2 < 2; j2++) {
                uint32_t q0, q1, q2, q3;
                ldsm4(q0, q1, q2, q3, bbase[j2] + so + ko);
                bf[j2*2  ][0] = q0; bf[j2*2  ][1] = q1;
                bf[j2*2+1][0] = q2; bf[j2*2+1][1] = q3;
            }
            #pragma unroll
            for (int i = 0; i < 2; i++)
                #pragma unroll
                for (int j = 0; j < 4; j++) {
                    float* c = acc[i*4 + j];
                    asm volatile(
                        "mma.sync.aligned.m16n8k16.row.col.f32.f16.f16.f32 "
                        "{%0,%1,%2,%3}, {%4,%5,%6,%7}, {%8,%9}, {%0,%1,%2,%3};"
                        : "+f"(c[0]), "+f"(c[1]), "+f"(c[2]), "+f"(c[3])
                        : "r"(af[i][0]), "r"(af[i][1]), "r"(af[i][2]), "r"(af[i][3]),
                          "r"(bf[j][0]), "r"(bf[j][1]));
                }
        }
    }

    const int g = lane >> 2, tg = lane & 3;
    #pragma unroll
    for (int i = 0; i < 2; i++) {
        #pragma unroll
        for (int j = 0; j < 4; j++) {
            int row = bm + wm + i*16 + g;
            int col = bn + wn + j*8 + (tg << 1);
            if (col >= N) continue;
            float* c = acc[i*4 + j];
            float2 v0 = make_float2(c[0], c[1]);
            float2 v1 = make_float2(c[2], c[3]);
            if (EPI == 1 || EPI == 3) {
                float2 bv = *(const float2*)&bias[col];
                v0.x += bv.x; v0.y += bv.y;
                v1.x += bv.x; v1.y += bv.y;
            }
            if (EPI == 1) {
                v0.x = geluf(v0.x); v0.y = geluf(v0.y);
                v1.x = geluf(v1.x); v1.y = geluf(v1.y);
            }
            if (EPI == 2 || EPI == 3) {
                float2 r0 = *(const float2*)&res[(size_t)row*N + col];
                float2 r1 = *(const float2*)&res[(size_t)(row+8)*N + col];
                v0.x += r0.x; v0.y += r0.y;
                v1.x += r1.x; v1.y += r1.y;
            }
            if (OUTH) {
                __half* Ch = (__half*)Cout;
                *(__half2*)&Ch[(size_t)row*N + col]     = __floats2half2_rn(v0.x, v0.y);
                *(__half2*)&Ch[(size_t)(row+8)*N + col] = __floats2half2_rn(v1.x, v1.y);
            } else {
                float* Cf = (float*)Cout;
                *(float2*)&Cf[(size_t)row*N + col]     = v0;
                *(float2*)&Cf[(size_t)(row+8)*N + col] = v1;
            }
        }
    }
}

// ---------------- dt preprocess ----------------
__global__ void dt_kernel(const float* __restrict__ zx, const float* __restrict__ dt_bias,
                          const float* __restrict__ A_log,
                          float* __restrict__ dec, float* __restrict__ dts)
{
    int idx = blockIdx.x * blockDim.x + threadIdx.x;
    int hh = idx & 15;
    int t  = (idx >> 4) & (SEQLEN - 1);
    int s  = idx >> 15;
    int b  = s & 3;
    int off = (s < 4) ? 0 : NHEADSN;
    float raw = zx[((size_t)b*SEQLEN + t)*DINPROJ + (DINNER + CONVDIM) + off + hh] + dt_bias[hh];
    float sp = (raw > 20.f) ? raw : log1pf(expf(raw));
    float Ah = -expf(A_log[hh]);
    dec[idx] = expf(Ah * sp);
    dts[idx] = sp;
}

// ---------------- depthwise causal conv7 + bias + silu ----------------
__global__ void conv_kernel(const float* __restrict__ zx, const float* __restrict__ cw,
                            const float* __restrict__ cb, float* __restrict__ out)
{
    int idx = blockIdx.x * blockDim.x + threadIdx.x;
    int c  = (idx % (CONVDIM/4)) << 2;
    int bt = idx / (CONVDIM/4);
    int t  = bt & (SEQLEN - 1);
    int b  = bt >> 11;
    float4 acc = *(const float4*)&cb[c];
    float w[4][7];
    #pragma unroll
    for (int k = 0; k < 4; k++)
        #pragma unroll
        for (int j = 0; j < 7; j++) w[k][j] = cw[(c+k)*7 + j];
    const float* base = zx + (size_t)b*SEQLEN*DINPROJ + DINNER + c;
    #pragma unroll
    for (int j = 0; j < 7; j++) {
        int tt = t - 6 + j;
        if (tt >= 0) {
            float4 v = *(const float4*)&base[(size_t)tt*DINPROJ];
            acc.x = fmaf(v.x, w[0][j], acc.x);
            acc.y = fmaf(v.y, w[1][j], acc.y);
            acc.z = fmaf(v.z, w[2][j], acc.z);
            acc.w = fmaf(v.w, w[3][j], acc.w);
        }
    }
    float4 o;
    o.x = siluf(acc.x); o.y = siluf(acc.y);
    o.z = siluf(acc.z); o.w = siluf(acc.w);
    *(float4*)&out[((size_t)bt*CONVDIM) + c] = o;
}

// ---------------- segmented scan phase 1: no-shuffle, smem-partial version ----------------
// sY[j][q][p] partials (stride 72 rows -> bank = p+8q, conflict-free), chunk reduce pass.
__global__ void __launch_bounds__(256) scan_seg1(
    const float* __restrict__ xbc, const float* __restrict__ dec,
    const float* __restrict__ dts, float* __restrict__ y,
    float* __restrict__ hf, float* __restrict__ cd)
{
    const int h = blockIdx.x, s = blockIdx.y, k = blockIdx.z;
    const int b = s & 3;
    const bool fw = (s < 4);
    const int tid = threadIdx.x;
    const int p = tid >> 2;
    const int q = tid & 3;

    __shared__ float sB[16][64], sC[16][64];
    __shared__ float sXt[64][20];        // transposed X, stride 20 -> conflict-free LDS.128
    __shared__ float sY[16*4*72];        // partials
    __shared__ float sDec[16], sDt[16];

    uint64_t h2[8];
    #pragma unroll
    for (int i = 0; i < 8; i++) h2[i] = 0ull;
    float cdv = 1.f;

    const float* base = xbc + (size_t)b*SEQLEN*CONVDIM;
    float* cdout = cd + ((size_t)s*NHEADSN + h)*SEQLEN;
    const int tau0 = k * SEGL;
    const int js = tid >> 4;             // 0..15
    const int n4 = (tid & 15) << 2;

    for (int cc = 0; cc < SEGL/16; cc++) {
        // staging
        {
            int tau = tau0 + cc*16 + js;
            int orig = fw ? tau : (SEQLEN - 1 - tau);
            const float* row = base + (size_t)orig*CONVDIM;
            float4 vx = *(const float4*)&row[h*HEADDIM + n4];
            *(float4*)&sB[js][n4] = *(const float4*)&row[DINNER + n4];
            *(float4*)&sC[js][n4] = *(const float4*)&row[DINNER + DSTATE + n4];
            sXt[n4+0][js] = vx.x; sXt[n4+1][js] = vx.y;
            sXt[n4+2][js] = vx.z; sXt[n4+3][js] = vx.w;
        }
        if (tid < 16) {
            int tau = tau0 + cc*16 + tid;
            int orig = fw ? tau : (SEQLEN - 1 - tau);
            size_t di = ((size_t)s*SEQLEN + orig)*NHEADSN + h;
            sDec[tid] = dec[di];
            sDt[tid]  = dts[di];
        }
        __syncthreads();

        // preload X for this thread's p across all 16 steps
        float xreg[16];
        {
            const float4* xp = (const float4*)&sXt[p][0];
            #pragma unroll
            for (int v = 0; v < 4; v++) {
                float4 xv = xp[v];
                xreg[v*4+0] = xv.x; xreg[v*4+1] = xv.y;
                xreg[v*4+2] = xv.z; xreg[v*4+3] = xv.w;
            }
        }

        #pragma unroll 4
        for (int j = 0; j < 16; j++) {
            float d   = sDec[j];
            float dtx = sDt[j] * xreg[j];
            cdv *= d;
            uint64_t d2   = pack2(d, d);
            uint64_t dtx2 = pack2(dtx, dtx);
            uint64_t ys0  = 0ull, ys1 = 0ull;
            const longlong2* B4 = (const longlong2*)&sB[j][q << 4];
            const longlong2* C4 = (const longlong2*)&sC[j][q << 4];
            #pragma unroll
            for (int v = 0; v < 4; v++) {
                longlong2 bb = B4[v], cv = C4[v];
                uint64_t t1;
                MUL2(t1, dtx2, (uint64_t)bb.x);
                FMA2_SELF_MUL(h2[2*v], d2, t1);
                FMA2_ACC(ys0, h2[2*v], (uint64_t)cv.x);
                MUL2(t1, dtx2, (uint64_t)bb.y);
                FMA2_SELF_MUL(h2[2*v+1], d2, t1);
                FMA2_ACC(ys1, h2[2*v+1], (uint64_t)cv.y);
            }
            float a0, a1, b0, b1;
            unpack2(ys0, a0, a1);
            unpack2(ys1, b0, b1);
            sY[(j*4 + q)*72 + p] = (a0 + a1) + (b0 + b1);
            if (tid == 0) cdout[tau0 + cc*16 + j] = cdv;
        }
        __syncthreads();

        // reduce pass: sum 4 q-partials, coalesced float4 store to y
        {
            int t  = tid >> 4;
            int i4 = (tid & 15) << 2;
            int tau = tau0 + cc*16 + t;
            int to = fw ? (tau + 1) : (SEQLEN - 2 - tau);
            if (to >= 0 && to < SEQLEN) {
                const float* r0 = &sY[(t*4 + 0)*72 + i4];
                const float* r1 = &sY[(t*4 + 1)*72 + i4];
                const float* r2 = &sY[(t*4 + 2)*72 + i4];
                const float* r3 = &sY[(t*4 + 3)*72 + i4];
                float4 v0 = *(const float4*)r0;
                float4 v1 = *(const float4*)r1;
                float4 v2 = *(const float4*)r2;
                float4 v3 = *(const float4*)r3;
                float4 o;
                o.x = (v0.x + v1.x) + (v2.x + v3.x);
                o.y = (v0.y + v1.y) + (v2.y + v3.y);
                o.z = (v0.z + v1.z) + (v2.z + v3.z);
                o.w = (v0.w + v1.w) + (v2.w + v3.w);
                *(float4*)&y[((size_t)s*SEQLEN + to)*DINNER + h*HEADDIM + i4] = o;
            }
        }
        __syncthreads();
    }

    uint64_t* hfp = (uint64_t*)(hf +
        ((((size_t)s*NHEADSN + h)*NSEG + k)*HEADDIM*DSTATE) + p*DSTATE + (q << 4));
    #pragma unroll
    for (int v = 0; v < 8; v++) hfp[v] = h2[v];
}

// ---------------- segmented scan phase 3: no-shuffle version ----------------
__global__ void __launch_bounds__(256) scan_seg3(
    const float* __restrict__ xbc, const float* __restrict__ cd,
    const float* __restrict__ hf, float* __restrict__ y)
{
    const int h = blockIdx.x, s = blockIdx.y, k = blockIdx.z + 1;
    const int b = s & 3;
    const bool fw = (s < 4);
    const int tid = threadIdx.x;
    const int p = tid >> 2;
    const int q = tid & 3;

    const float* cdb = cd + ((size_t)s*NHEADSN + h)*SEQLEN;

    uint64_t H[8];
    #pragma unroll
    for (int v = 0; v < 8; v++) H[v] = 0ull;
    for (int j = 0; j < k; j++) {
        float Pj = cdb[j*SEGL + SEGL - 1];
        uint64_t P2 = pack2(Pj, Pj);
        const uint64_t* hfp = (const uint64_t*)(hf +
            ((((size_t)s*NHEADSN + h)*NSEG + j)*HEADDIM*DSTATE) + p*DSTATE + (q << 4));
        #pragma unroll
        for (int v = 0; v < 8; v++) {
            uint64_t hv = hfp[v];
            FMA2_SELF_MUL(H[v], P2, hv);
        }
    }

    __shared__ float sC[16][64];
    __shared__ float sY[16*4*72];
    __shared__ float sCd[16];
    const float* cbase = xbc + (size_t)b*SEQLEN*CONVDIM + DINNER + DSTATE;
    const int tau0 = k * SEGL;
    const int js = tid >> 4;
    const int n4 = (tid & 15) << 2;

    for (int cc = 0; cc < SEGL/16; cc++) {
        {
            int tau = tau0 + cc*16 + js;
            int orig = fw ? tau : (SEQLEN - 1 - tau);
            *(float4*)&sC[js][n4] = *(const float4*)&cbase[(size_t)orig*CONVDIM + n4];
        }
        if (tid < 16) sCd[tid] = cdb[tau0 + cc*16 + tid];
        __syncthreads();

        #pragma unroll 4
        for (int j = 0; j < 16; j++) {
            uint64_t ys0 = 0ull, ys1 = 0ull;
            const longlong2* C4 = (const longlong2*)&sC[j][q << 4];
            #pragma unroll
            for (int v = 0; v < 4; v++) {
                longlong2 cv = C4[v];
                FMA2_ACC(ys0, H[2*v],   (uint64_t)cv.x);
                FMA2_ACC(ys1, H[2*v+1], (uint64_t)cv.y);
            }
            float a0, a1, b0, b1;
            unpack2(ys0, a0, a1);
            unpack2(ys1, b0, b1);
            sY[(j*4 + q)*72 + p] = (a0 + a1) + (b0 + b1);
        }
        __syncthreads();

        // reduce + RMW into y
        {
            int t  = tid >> 4;
            int i4 = (tid & 15) << 2;
            int tau = tau0 + cc*16 + t;
            int to = fw ? (tau + 1) : (SEQLEN - 2 - tau);
            if (to >= 0 && to < SEQLEN) {
                float4 v0 = *(const float4*)&sY[(t*4 + 0)*72 + i4];
                float4 v1 = *(const float4*)&sY[(t*4 + 1)*72 + i4];
                float4 v2 = *(const float4*)&sY[(t*4 + 2)*72 + i4];
                float4 v3 = *(const float4*)&sY[(t*4 + 3)*72 + i4];
                float cdt = sCd[t];
                float* yp = &y[((size_t)s*SEQLEN + to)*DINNER + h*HEADDIM + i4];
                float4 old = *(float4*)yp;
                float4 o;
                o.x = old.x + cdt*((v0.x + v1.x) + (v2.x + v3.x));
                o.y = old.y + cdt*((v0.y + v1.y) + (v2.y + v3.y));
                o.z = old.z + cdt*((v0.z + v1.z) + (v2.z + v3.z));
                o.w = old.w + cdt*((v0.w + v1.w) + (v2.w + v3.w));
                *(float4*)yp = o;
            }
        }
        __syncthreads();
    }
}

// ---------------- gating + D skip + RMS norm (fp16 output) ----------------
__global__ void __launch_bounds__(256) gate_rms_kernel(
    const float* __restrict__ y, const float* __restrict__ xbc,
    const float* __restrict__ zx, const float* __restrict__ Dp,
    const float* __restrict__ rms_w, __half* __restrict__ out)
{
    int row = blockIdx.x;
    int b = row >> 11, t = row & 2047;
    int c = threadIdx.x << 2;
    size_t ybase = ((size_t)b*SEQLEN + t)*DINNER + c;
    const float4 yf = *(const float4*)&y[ybase];
    const float4 yb = *(const float4*)&y[ybase + (size_t)4*SEQLEN*DINNER];
    const float4 xo = *(const float4*)&xbc[((size_t)b*SEQLEN + t)*CONVDIM + c];
    const float4 zv = *(const float4*)&zx[((size_t)b*SEQLEN + t)*DINPROJ + c];
    float dp = Dp[c >> 6];
    float g0 = (yf.x + yb.x + xo.x*dp) * siluf(zv.x);
    float g1 = (yf.y + yb.y + xo.y*dp) * siluf(zv.y);
    float g2 = (yf.z + yb.z + xo.z*dp) * siluf(zv.z);
    float g3 = (yf.w + yb.w + xo.w*dp) * siluf(zv.w);
    float ss = g0*g0 + g1*g1 + g2*g2 + g3*g3;
    #pragma unroll
    for (int o = 16; o > 0; o >>= 1)
        ss += __shfl_xor_sync(0xffffffffu, ss, o);
    __shared__ float asum[8];
    int wid = threadIdx.x >> 5;
    if ((threadIdx.x & 31) == 0) asum[wid] = ss;
    __syncthreads();
    ss = asum[0]+asum[1]+asum[2]+asum[3]+asum[4]+asum[5]+asum[6]+asum[7];
    float scale = rsqrtf(ss * (1.0f/DINNER) + EPSV);
    const float4 wv = *(const float4*)&rms_w[c];
    __half2* op = (__half2*)(out + (size_t)row*DINNER + c);
    op[0] = __floats2half2_rn(g0*scale*wv.x, g1*scale*wv.y);
    op[1] = __floats2half2_rn(g2*scale*wv.z, g3*scale*wv.w);
}

// ---------------- launcher ----------------
extern "C" void kernel_launch(void* const* d_in, const int* in_sizes, int n_in,
                              void* d_out, int out_size)
{
    const float* x         = (const float*)d_in[0];
    const float* ln1_w     = (const float*)d_in[1];
    const float* ln1_b     = (const float*)d_in[2];
    const float* in_proj_w = (const float*)d_in[3];
    const float* conv_w    = (const float*)d_in[4];
    const float* conv_b    = (const float*)d_in[5];
    const float* dt_bias   = (const float*)d_in[6];
    const float* A_log     = (const float*)d_in[7];
    const float* Dp        = (const float*)d_in[8];
    const float* rms_w     = (const float*)d_in[9];
    const float* out_proj_w= (const float*)d_in[10];
    const float* ln2_w     = (const float*)d_in[11];
    const float* ln2_b     = (const float*)d_in[12];
    const float* fc1_w     = (const float*)d_in[13];
    const float* fc1_b     = (const float*)d_in[14];
    const float* fc2_w     = (const float*)d_in[15];
    const float* fc2_b     = (const float*)d_in[16];
    float* out = (float*)d_out;

    float *zx, *xbc, *dec, *dts, *y, *x2, *hf, *cdp;
    __half *h16, *yg16, *ff1h, *wip, *wop, *w1, *w2;
    cudaGetSymbolAddress((void**)&zx,  g_zx);
    cudaGetSymbolAddress((void**)&xbc, g_xbc);
    cudaGetSymbolAddress((void**)&dec, g_dec);
    cudaGetSymbolAddress((void**)&dts, g_dts);
    cudaGetSymbolAddress((void**)&y,   g_y);
    cudaGetSymbolAddress((void**)&x2,  g_x2);
    cudaGetSymbolAddress((void**)&hf,  g_hf);
    cudaGetSymbolAddress((void**)&cdp, g_cd);
    cudaGetSymbolAddress((void**)&h16, g_h16);
    cudaGetSymbolAddress((void**)&yg16,g_yg16);
    cudaGetSymbolAddress((void**)&ff1h,g_ff1h);
    cudaGetSymbolAddress((void**)&wip, g_wip);
    cudaGetSymbolAddress((void**)&wop, g_wop);
    cudaGetSymbolAddress((void**)&w1,  g_w1);
    cudaGetSymbolAddress((void**)&w2,  g_w2);

    cudaFuncSetAttribute(gemm_h<0,0>, cudaFuncAttributeMaxDynamicSharedMemorySize, GEMM_SMEM);
    cudaFuncSetAttribute(gemm_h<1,1>, cudaFuncAttributeMaxDynamicSharedMemorySize, GEMM_SMEM);
    cudaFuncSetAttribute(gemm_h<2,0>, cudaFuncAttributeMaxDynamicSharedMemorySize, GEMM_SMEM);
    cudaFuncSetAttribute(gemm_h<3,0>, cudaFuncAttributeMaxDynamicSharedMemorySize, GEMM_SMEM);

    // 0. fused weight conversion
    {
        int n0 = DINPROJ*DMODEL, n1 = DMODEL*DINNER, n2 = DFF*DMODEL, n3 = DMODEL*DFF;
        int total4 = (n0+n1+n2+n3) >> 2;
        cvt_all_kernel<<<(total4 + 255)/256, 256>>>(
            in_proj_w, wip, n0, out_proj_w, wop, n1, fc1_w, w1, n2, fc2_w, w2, n3);
    }
    // 1. LN1
    ln_kernel<<<NROWS, 128>>>(x, ln1_w, ln1_b, h16);
    // 2. scan boundary zero
    zb_kernel<<<8, 256>>>(y);
    // 3. in_proj (launch #4 — profiled)
    gemm_h<0,0><<<dim3((DINPROJ + 127)/128, NROWS/128), 512, GEMM_SMEM>>>(
        h16, wip, nullptr, nullptr, zx, NROWS, DINPROJ, DMODEL);
    // 4. dt preprocess
    dt_kernel<<<(8*SEQLEN*NHEADSN)/256, 256>>>(zx, dt_bias, A_log, dec, dts);
    // 5. conv + silu
    conv_kernel<<<(NROWS*CONVDIM/4)/256, 256>>>(zx, conv_w, conv_b, xbc);
    // 6. segmented scan: local scans (1024 blocks)
    scan_seg1<<<dim3(NHEADSN, 8, NSEG), 256>>>(xbc, dec, dts, y, hf, cdp);
    // 7. segmented scan: cross-segment fixup (896 blocks)
    scan_seg3<<<dim3(NHEADSN, 8, NSEG-1), 256>>>(xbc, cdp, hf, y);
    // 8. gate + D skip + RMS norm
    gate_rms_kernel<<<NROWS, 256>>>(y, xbc, zx, Dp, rms_w, yg16);
    // 9. out_proj + residual(x)
    gemm_h<2,0><<<dim3(DMODEL/128, NROWS/128), 512, GEMM_SMEM>>>(
        yg16, wop, nullptr, x, x2, NROWS, DMODEL, DINNER);
    // 10. LN2
    ln_kernel<<<NROWS, 128>>>(x2, ln2_w, ln2_b, h16);
    // 11. fc1 + bias + gelu
    gemm_h<1,1><<<dim3(DFF/128, NROWS/128), 512, GEMM_SMEM>>>(
        h16, w1, fc1_b, nullptr, ff1h, NROWS, DFF, DMODEL);
    // 12. fc2 + bias + residual(x2) -> d_out
    gemm_h<3,0><<<dim3(DMODEL/128, NROWS/128), 512, GEMM_SMEM>>>(
        ff1h, w2, fc2_b, x2, out, NROWS, DMODEL, DFF);
}

// round 15
// speedup vs baseline: 2.3796x; 2.2094x over previous
#include <cuda_runtime.h>
#include <cuda_fp16.h>
#include <math.h>
#include <stdint.h>

// ---------------- problem constants ----------------
#define BATCHN  4
#define SEQLEN  2048
#define DMODEL  512
#define DINNER  1024
#define NHEADSN 16
#define HEADDIM 64
#define DSTATE  64
#define CONVDIM 1152
#define DINPROJ 2208
#define DFF     2048
#define NROWS   (BATCHN*SEQLEN)   // 8192
#define EPSV    1e-5f
#define CHUNK   64
#define NCH     32                // SEQLEN/CHUNK
#define SPAD    72                // halves per smem row (144B, 16B-aligned, bank-rotating)

// ---------------- scratch ----------------
__device__ float  g_zx  [NROWS*DINPROJ];
__device__ float  g_xbc [NROWS*CONVDIM];
__device__ float  g_ld  [8*SEQLEN*NHEADSN];   // log-decay
__device__ float  g_dts [8*SEQLEN*NHEADSN];
__device__ float  g_y   [8*SEQLEN*DINNER];
__device__ float  g_x2  [NROWS*DMODEL];
__device__ float  g_hf  [8*NHEADSN*NCH*HEADDIM*DSTATE];   // chunk-local final states
__device__ float  g_hp  [8*NHEADSN*NCH*HEADDIM*DSTATE];   // prefix (incoming) states
__device__ float  g_cd  [8*NHEADSN*SEQLEN];               // within-chunk cum decay
__device__ __half g_h16 [NROWS*DMODEL];
__device__ __half g_yg16[NROWS*DINNER];
__device__ __half g_ff1h[NROWS*DFF];
__device__ __half g_wip [DINPROJ*DMODEL];
__device__ __half g_wop [DMODEL*DINNER];
__device__ __half g_w1  [DFF*DMODEL];
__device__ __half g_w2  [DMODEL*DFF];

// ---------------- helpers ----------------
__device__ __forceinline__ float geluf(float x) {
    return 0.5f * x * (1.0f + erff(x * 0.70710678118654752f));
}
__device__ __forceinline__ float siluf(float x) {
    return x / (1.0f + expf(-x));
}

#define CP16(dst, src) \
    asm volatile("cp.async.cg.shared.global [%0], [%1], 16;" :: "r"(dst), "l"(src))
#define CP16Z(dst, src, sz) \
    asm volatile("cp.async.cg.shared.global [%0], [%1], 16, %2;" :: "r"(dst), "l"(src), "r"(sz))
#define CP_COMMIT() asm volatile("cp.async.commit_group;")
#define CP_WAIT2()  asm volatile("cp.async.wait_group 2;")

__device__ __forceinline__ void ldsm4(uint32_t& q0, uint32_t& q1, uint32_t& q2, uint32_t& q3,
                                      uint32_t addr) {
    asm volatile("ldmatrix.sync.aligned.m8n8.x4.shared.b16 {%0,%1,%2,%3}, [%4];"
        : "=r"(q0), "=r"(q1), "=r"(q2), "=r"(q3) : "r"(addr));
}
#define MMA16816(c, a, b) \
    asm volatile("mma.sync.aligned.m16n8k16.row.col.f32.f16.f16.f32 " \
        "{%0,%1,%2,%3}, {%4,%5,%6,%7}, {%8,%9}, {%0,%1,%2,%3};" \
        : "+f"((c)[0]), "+f"((c)[1]), "+f"((c)[2]), "+f"((c)[3]) \
        : "r"((a)[0]), "r"((a)[1]), "r"((a)[2]), "r"((a)[3]), "r"((b)[0]), "r"((b)[1]))

// ---------------- fused f32 -> f16 weight convert ----------------
__global__ void cvt_all_kernel(
    const float* __restrict__ s0, __half* __restrict__ d0, int n0,
    const float* __restrict__ s1, __half* __restrict__ d1, int n1,
    const float* __restrict__ s2, __half* __restrict__ d2, int n2,
    const float* __restrict__ s3, __half* __restrict__ d3, int n3)
{
    int i = (blockIdx.x*blockDim.x + threadIdx.x) << 2;
    const float* s; __half* d;
    if (i < n0)                    { s = s0;      d = d0; }
    else if (i < n0+n1)            { s = s1 - n0; d = d1 - n0; }
    else if (i < n0+n1+n2)         { s = s2 - (n0+n1); d = d2 - (n0+n1); }
    else if (i < n0+n1+n2+n3)      { s = s3 - (n0+n1+n2); d = d3 - (n0+n1+n2); }
    else return;
    float4 v = *(const float4*)&s[i];
    *(__half2*)&d[i]   = __floats2half2_rn(v.x, v.y);
    *(__half2*)&d[i+2] = __floats2half2_rn(v.z, v.w);
}

// ---------------- scan boundary zero ----------------
__global__ void zb_kernel(float* __restrict__ y)
{
    int s = blockIdx.x;
    int t0 = (s < 4) ? 0 : (SEQLEN - 1);
    float4* p = (float4*)(y + ((size_t)s*SEQLEN + t0)*DINNER);
    p[threadIdx.x] = make_float4(0.f, 0.f, 0.f, 0.f);
}

// ---------------- LayerNorm (D=512), fp16 output ----------------
__global__ void __launch_bounds__(128) ln_kernel(
    const float* __restrict__ x, const float* __restrict__ w,
    const float* __restrict__ b, __half* __restrict__ out)
{
    int row = blockIdx.x;
    int tid = threadIdx.x;
    const float4 v = ((const float4*)(x + (size_t)row*DMODEL))[tid];
    float s  = v.x + v.y + v.z + v.w;
    float ss = v.x*v.x + v.y*v.y + v.z*v.z + v.w*v.w;
    #pragma unroll
    for (int o = 16; o > 0; o >>= 1) {
        s  += __shfl_xor_sync(0xffffffffu, s,  o);
        ss += __shfl_xor_sync(0xffffffffu, ss, o);
    }
    __shared__ float as[4], ass[4];
    int wid = tid >> 5;
    if ((tid & 31) == 0) { as[wid] = s; ass[wid] = ss; }
    __syncthreads();
    s  = as[0] + as[1] + as[2] + as[3];
    ss = ass[0] + ass[1] + ass[2] + ass[3];
    float mean = s * (1.0f/DMODEL);
    float var  = ss * (1.0f/DMODEL) - mean*mean;
    float rstd = rsqrtf(var + EPSV);
    const float4 wv = ((const float4*)w)[tid];
    const float4 bv = ((const float4*)b)[tid];
    float o0 = (v.x - mean)*rstd*wv.x + bv.x;
    float o1 = (v.y - mean)*rstd*wv.y + bv.y;
    float o2 = (v.z - mean)*rstd*wv.z + bv.z;
    float o3 = (v.w - mean)*rstd*wv.w + bv.w;
    __half2* op = (__half2*)(out + (size_t)row*DMODEL + (tid << 2));
    op[0] = __floats2half2_rn(o0, o1);
    op[1] = __floats2half2_rn(o2, o3);
}

// ---------------- fp16 tensor-core GEMM (f32 accum) ----------------
#define NSTAGE  4
#define ROWB    80
#define OPSTAGE (128*ROWB)
#define SMBOFF  (NSTAGE*OPSTAGE)
#define GEMM_SMEM (2*NSTAGE*OPSTAGE)

template<int EPI, int OUTH>
__global__ void __launch_bounds__(512) gemm_h(
    const __half* __restrict__ A, const __half* __restrict__ W,
    const float* __restrict__ bias, const float* __restrict__ res,
    void* __restrict__ Cout, int M, int N, int K)
{
    extern __shared__ char smem[];
    const uint32_t su = (uint32_t)__cvta_generic_to_shared(smem);
    const int tid = threadIdx.x, lane = tid & 31, wid = tid >> 5;
    const int bm = blockIdx.y << 7, bn = blockIdx.x << 7;
    const int wm = (wid & 3)  << 5;
    const int wn = (wid >> 2) << 5;
    const int ntiles = K >> 5;

    const int lrow = tid >> 2;
    const int lcp  = tid & 3;
    const int an = bn + lrow;
    const uint32_t bsz = (an < N) ? 16u : 0u;
    const __half* aSrc = A + (size_t)(bm + lrow)*K + (lcp << 3);
    const __half* bSrc = W + (size_t)((an < N) ? an : 0)*K + (lcp << 3);
    const uint32_t dA = su + lrow*ROWB + (lcp << 4);
    const uint32_t dB = dA + SMBOFF;

    const int arow = ((lane >> 3) & 1)*8 + (lane & 7);
    const int abyt = (lane >> 4) << 4;
    uint32_t abase[2];
    #pragma unroll
    for (int i = 0; i < 2; i++)
        abase[i] = su + (wm + i*16 + arow)*ROWB + abyt;
    const int brow = (lane >> 4)*8 + (lane & 7);
    const int bbyt = ((lane >> 3) & 1) << 4;
    uint32_t bbase[2];
    #pragma unroll
    for (int j2 = 0; j2 < 2; j2++)
        bbase[j2] = su + SMBOFF + (wn + j2*16 + brow)*ROWB + bbyt;

    float acc[8][4];
    #pragma unroll
    for (int i = 0; i < 8; i++) { acc[i][0]=acc[i][1]=acc[i][2]=acc[i][3]=0.f; }

    auto issue_tile = [&](int tf) {
        const uint32_t so = (tf & (NSTAGE-1))*OPSTAGE;
        const int kh = tf << 5;
        CP16 (dA + so, aSrc + kh);
        CP16Z(dB + so, bSrc + kh, bsz);
    };

    issue_tile(0); CP_COMMIT();
    issue_tile(1); CP_COMMIT();
    issue_tile(2); CP_COMMIT();

    for (int t = 0; t < ntiles; t++) {
        CP_WAIT2();
        __syncthreads();
        if (t + 3 < ntiles) issue_tile(t + 3);
        CP_COMMIT();

        const uint32_t so = (t & (NSTAGE-1))*OPSTAGE;
        #pragma unroll
        for (int ks = 0; ks < 2; ks++) {
            const uint32_t ko = ks << 5;
            uint32_t af[2][4], bf[4][2];
            #pragma unroll
            for (int i = 0; i < 2; i++)
                ldsm4(af[i][0], af[i][1], af[i][2], af[i][3], abase[i] + so + ko);
            #pragma unroll
            for (int j2 = 0; j2 < 2; j2++) {
                uint32_t q0, q1, q2, q3;
                ldsm4(q0, q1, q2, q3, bbase[j2] + so + ko);
                bf[j2*2  ][0] = q0; bf[j2*2  ][1] = q1;
                bf[j2*2+1][0] = q2; bf[j2*2+1][1] = q3;
            }
            #pragma unroll
            for (int i = 0; i < 2; i++)
                #pragma unroll
                for (int j = 0; j < 4; j++)
                    MMA16816(acc[i*4 + j], af[i], bf[j]);
        }
    }

    const int g = lane >> 2, tg = lane & 3;
    #pragma unroll
    for (int i = 0; i < 2; i++) {
        #pragma unroll
        for (int j = 0; j < 4; j++) {
            int row = bm + wm + i*16 + g;
            int col = bn + wn + j*8 + (tg << 1);
            if (col >= N) continue;
            float* c = acc[i*4 + j];
            float2 v0 = make_float2(c[0], c[1]);
            float2 v1 = make_float2(c[2], c[3]);
            if (EPI == 1 || EPI == 3) {
                float2 bv = *(const float2*)&bias[col];
                v0.x += bv.x; v0.y += bv.y;
                v1.x += bv.x; v1.y += bv.y;
            }
            if (EPI == 1) {
                v0.x = geluf(v0.x); v0.y = geluf(v0.y);
                v1.x = geluf(v1.x); v1.y = geluf(v1.y);
            }
            if (EPI == 2 || EPI == 3) {
                float2 r0 = *(const float2*)&res[(size_t)row*N + col];
                float2 r1 = *(const float2*)&res[(size_t)(row+8)*N + col];
                v0.x += r0.x; v0.y += r0.y;
                v1.x += r1.x; v1.y += r1.y;
            }
            if (OUTH) {
                __half* Ch = (__half*)Cout;
                *(__half2*)&Ch[(size_t)row*N + col]     = __floats2half2_rn(v0.x, v0.y);
                *(__half2*)&Ch[(size_t)(row+8)*N + col] = __floats2half2_rn(v1.x, v1.y);
            } else {
                float* Cf = (float*)Cout;
                *(float2*)&Cf[(size_t)row*N + col]     = v0;
                *(float2*)&Cf[(size_t)(row+8)*N + col] = v1;
            }
        }
    }
}

// ---------------- dt preprocess (now emits LOG decay) ----------------
__global__ void dt_kernel(const float* __restrict__ zx, const float* __restrict__ dt_bias,
                          const float* __restrict__ A_log,
                          float* __restrict__ ldec, float* __restrict__ dts)
{
    int idx = blockIdx.x * blockDim.x + threadIdx.x;
    int hh = idx & 15;
    int t  = (idx >> 4) & (SEQLEN - 1);
    int s  = idx >> 15;
    int b  = s & 3;
    int off = (s < 4) ? 0 : NHEADSN;
    float raw = zx[((size_t)b*SEQLEN + t)*DINPROJ + (DINNER + CONVDIM) + off + hh] + dt_bias[hh];
    float sp = (raw > 20.f) ? raw : log1pf(expf(raw));
    float Ah = -expf(A_log[hh]);
    ldec[idx] = Ah * sp;       // log decay
    dts[idx]  = sp;
}

// ---------------- depthwise causal conv7 + bias + silu ----------------
__global__ void conv_kernel(const float* __restrict__ zx, const float* __restrict__ cw,
                            const float* __restrict__ cb, float* __restrict__ out)
{
    int idx = blockIdx.x * blockDim.x + threadIdx.x;
    int c  = (idx % (CONVDIM/4)) << 2;
    int bt = idx / (CONVDIM/4);
    int t  = bt & (SEQLEN - 1);
    int b  = bt >> 11;
    float4 acc = *(const float4*)&cb[c];
    float w[4][7];
    #pragma unroll
    for (int k = 0; k < 4; k++)
        #pragma unroll
        for (int j = 0; j < 7; j++) w[k][j] = cw[(c+k)*7 + j];
    const float* base = zx + (size_t)b*SEQLEN*DINPROJ + DINNER + c;
    #pragma unroll
    for (int j = 0; j < 7; j++) {
        int tt = t - 6 + j;
        if (tt >= 0) {
            float4 v = *(const float4*)&base[(size_t)tt*DINPROJ];
            acc.x = fmaf(v.x, w[0][j], acc.x);
            acc.y = fmaf(v.y, w[1][j], acc.y);
            acc.z = fmaf(v.z, w[2][j], acc.z);
            acc.w = fmaf(v.w, w[3][j], acc.w);
        }
    }
    float4 o;
    o.x = siluf(acc.x); o.y = siluf(acc.y);
    o.z = siluf(acc.z); o.w = siluf(acc.w);
    *(float4*)&out[((size_t)bt*CONVDIM) + c] = o;
}

// ---------------- SSD scan phase 1: per-chunk GEMMs ----------------
// grid (16 heads, 8 seqs, 32 chunks), 128 threads (4 warps, each 16 output rows).
// Computes y_local (H_in = 0), chunk-final state hf, within-chunk cum-decay cd.
__global__ void __launch_bounds__(128) scan_chunk(
    const float* __restrict__ xbc, const float* __restrict__ ldec,
    const float* __restrict__ dts, float* __restrict__ y,
    float* __restrict__ hf, float* __restrict__ cd)
{
    const int h = blockIdx.x, s = blockIdx.y, k = blockIdx.z;
    const int b = s & 3;
    const bool fw = (s < 4);
    const int tid = threadIdx.x, lane = tid & 31, w = tid >> 5;

    __shared__ __half hC[64*SPAD], hB[64*SPAD], hXt[64*SPAD], hBt[64*SPAD], hS[64*SPAD];
    __shared__ float sLd[64], sDt[64];

    const float* base = xbc + (size_t)b*SEQLEN*CONVDIM;
    const int tau0 = k * CHUNK;

    // stage B, C, Bt, Xt (fp32 -> fp16)
    for (int i = tid; i < 64*64; i += 128) {
        int t = i >> 6, n = i & 63;
        int orig = fw ? (tau0 + t) : (SEQLEN - 1 - (tau0 + t));
        const float* row = base + (size_t)orig*CONVDIM;
        float bv = row[DINNER + n];
        float cv = row[DINNER + DSTATE + n];
        float xv = row[h*HEADDIM + n];      // n acting as p
        hB [t*SPAD + n] = __float2half(bv);
        hBt[n*SPAD + t] = __float2half(bv);
        hC [t*SPAD + n] = __float2half(cv);
        hXt[n*SPAD + t] = __float2half(xv); // Xt[p][tau]
    }
    // log-decay prefix + dt
    if (tid < 64) {
        int orig = fw ? (tau0 + tid) : (SEQLEN - 1 - (tau0 + tid));
        size_t di = ((size_t)s*SEQLEN + orig)*NHEADSN + h;
        float v = ldec[di];
        sDt[tid] = dts[di];
        #pragma unroll
        for (int d = 1; d < 32; d <<= 1) {
            float o = __shfl_up_sync(0xffffffffu, v, d);
            if (lane >= d) v += o;
        }
        sLd[tid] = v;
    }
    __syncthreads();
    if (tid >= 32 && tid < 64) sLd[tid] += sLd[31];
    __syncthreads();
    if (tid < 64)
        cd[((size_t)s*NHEADSN + h)*SEQLEN + tau0 + tid] = __expf(sLd[tid]);

    // fragment addressing (stride SPAD halves = 144B)
    const int arow = ((lane >> 3) & 1)*8 + (lane & 7);
    const int abyt = (lane >> 4) << 4;
    const int brow = (lane >> 4)*8 + (lane & 7);
    const int bbyt = ((lane >> 3) & 1) << 4;
    const uint32_t uC  = (uint32_t)__cvta_generic_to_shared(hC);
    const uint32_t uB  = (uint32_t)__cvta_generic_to_shared(hB);
    const uint32_t uXt = (uint32_t)__cvta_generic_to_shared(hXt);
    const uint32_t uBt = (uint32_t)__cvta_generic_to_shared(hBt);
    const uint32_t uS  = (uint32_t)__cvta_generic_to_shared(hS);
    const uint32_t aoff = (uint32_t)((16*w + arow)*(SPAD*2) + abyt);

    // ---- GEMM1: S = C @ B^T ----
    float accS[8][4];
    #pragma unroll
    for (int j = 0; j < 8; j++) { accS[j][0]=accS[j][1]=accS[j][2]=accS[j][3]=0.f; }
    #pragma unroll
    for (int kk = 0; kk < 4; kk++) {
        const uint32_t ko = kk << 5;
        uint32_t af[4];
        ldsm4(af[0], af[1], af[2], af[3], uC + aoff + ko);
        #pragma unroll
        for (int j2 = 0; j2 < 4; j2++) {
            uint32_t q0, q1, q2, q3;
            ldsm4(q0, q1, q2, q3, uB + (uint32_t)((j2*16 + brow)*(SPAD*2) + bbyt) + ko);
            uint32_t b0[2] = {q0, q1}, b1[2] = {q2, q3};
            MMA16816(accS[j2*2],     af, b0);
            MMA16816(accS[j2*2 + 1], af, b1);
        }
    }
    // mask + scale -> hS (fp16)
    {
        const int g = lane >> 2, tg = lane & 3;
        const int t0 = 16*w + g;
        #pragma unroll
        for (int j = 0; j < 8; j++) {
            int tc = 8*j + (tg << 1);
            float d0 = sDt[tc], d1 = sDt[tc+1];
            float l0 = sLd[tc], l1 = sLd[tc+1];
            #pragma unroll
            for (int r = 0; r < 2; r++) {
                int t = t0 + 8*r;
                float lt = sLd[t];
                float m0 = (tc     <= t) ? __expf(lt - l0)*d0 : 0.f;
                float m1 = (tc + 1 <= t) ? __expf(lt - l1)*d1 : 0.f;
                *(__half2*)&hS[t*SPAD + tc] =
                    __floats2half2_rn(accS[j][2*r]*m0, accS[j][2*r+1]*m1);
            }
        }
    }
    __syncthreads();   // GEMM1 reads of hB done; hS written

    // overwrite hB with Xw[p][tau] = X[tau][p] * w_tau
    {
        float ldl = sLd[63];
        for (int i = tid; i < 64*64; i += 128) {
            int p = i >> 6, t = i & 63;
            float wv = __expf(ldl - sLd[t]) * sDt[t];
            hB[p*SPAD + t] = __float2half(__half2float(hXt[p*SPAD + t]) * wv);
        }
    }
    __syncthreads();

    // ---- GEMM2: Y = S' @ X  (B-op = Xt rows [p][tau]) ----
    // ---- GEMM3: H = Xw @ B  (A = hB-as-Xw rows [p][tau], B-op = Bt rows [n][tau]) ----
    float accY[8][4], accH[8][4];
    #pragma unroll
    for (int j = 0; j < 8; j++) {
        accY[j][0]=accY[j][1]=accY[j][2]=accY[j][3]=0.f;
        accH[j][0]=accH[j][1]=accH[j][2]=accH[j][3]=0.f;
    }
    #pragma unroll
    for (int kk = 0; kk < 4; kk++) {
        const uint32_t ko = kk << 5;
        uint32_t afS[4], afW[4];
        ldsm4(afS[0], afS[1], afS[2], afS[3], uS + aoff + ko);
        ldsm4(afW[0], afW[1], afW[2], afW[3], uB + aoff + ko);
        #pragma unroll
        for (int j2 = 0; j2 < 4; j2++) {
            const uint32_t bo = (uint32_t)((j2*16 + brow)*(SPAD*2) + bbyt) + ko;
            uint32_t q0, q1, q2, q3;
            ldsm4(q0, q1, q2, q3, uXt + bo);
            { uint32_t b0[2]={q0,q1}, b1[2]={q2,q3};
              MMA16816(accY[j2*2], afS, b0); MMA16816(accY[j2*2+1], afS, b1); }
            ldsm4(q0, q1, q2, q3, uBt + bo);
            { uint32_t b0[2]={q0,q1}, b1[2]={q2,q3};
              MMA16816(accH[j2*2], afW, b0); MMA16816(accH[j2*2+1], afW, b1); }
        }
    }

    // store outputs
    {
        const int g = lane >> 2, tg = lane & 3;
        const int r0 = 16*w + g;
        float* hfp = hf + ((((size_t)s*NHEADSN + h)*NCH + k)*HEADDIM*DSTATE);
        #pragma unroll
        for (int j = 0; j < 8; j++) {
            int col = 8*j + (tg << 1);
            #pragma unroll
            for (int r = 0; r < 2; r++) {
                int row = r0 + 8*r;
                // Y -> y (shifted)
                int taug = tau0 + row;
                int to = fw ? (taug + 1) : (SEQLEN - 2 - taug);
                if (to >= 0 && to < SEQLEN) {
                    float2 v = make_float2(accY[j][2*r], accY[j][2*r+1]);
                    *(float2*)&y[((size_t)s*SEQLEN + to)*DINNER + h*HEADDIM + col] = v;
                }
                // H -> hf
                float2 hv = make_float2(accH[j][2*r], accH[j][2*r+1]);
                *(float2*)&hfp[row*DSTATE + col] = hv;
            }
        }
    }
}

// ---------------- SSD scan phase 2: serial chunk-state combine ----------------
// grid (16 heads, 8 seqs), 256 threads; each thread owns 16 contiguous state floats.
__global__ void __launch_bounds__(256) scan_combine(
    const float* __restrict__ hf, const float* __restrict__ cd,
    float* __restrict__ hp)
{
    const int h = blockIdx.x, s = blockIdx.y;
    const int off = threadIdx.x << 4;
    const size_t base = ((size_t)s*NHEADSN + h)*NCH*HEADDIM*DSTATE;
    const float* cdb = cd + ((size_t)s*NHEADSN + h)*SEQLEN;
    float prev[16];
    #pragma unroll
    for (int i = 0; i < 16; i++) prev[i] = 0.f;
    for (int k = 0; k < NCH; k++) {
        float4* dst = (float4*)(hp + base + (size_t)k*HEADDIM*DSTATE + off);
        #pragma unroll
        for (int v = 0; v < 4; v++)
            dst[v] = make_float4(prev[4*v], prev[4*v+1], prev[4*v+2], prev[4*v+3]);
        float P = cdb[k*CHUNK + CHUNK - 1];
        const float4* src = (const float4*)(hf + base + (size_t)k*HEADDIM*DSTATE + off);
        #pragma unroll
        for (int v = 0; v < 4; v++) {
            float4 hv = src[v];
            prev[4*v+0] = fmaf(prev[4*v+0], P, hv.x);
            prev[4*v+1] = fmaf(prev[4*v+1], P, hv.y);
            prev[4*v+2] = fmaf(prev[4*v+2], P, hv.z);
            prev[4*v+3] = fmaf(prev[4*v+3], P, hv.w);
        }
    }
}

// ---------------- SSD scan phase 3: cross-chunk fixup y += cd_t * (C_t . H_in) ----------------
// grid (16 heads, 8 seqs, 31 chunks k=1..31), 128 threads.
__global__ void __launch_bounds__(128) scan_fix(
    const float* __restrict__ xbc, const float* __restrict__ cd,
    const float* __restrict__ hp, float* __restrict__ y)
{
    const int h = blockIdx.x, s = blockIdx.y, k = blockIdx.z + 1;
    const int b = s & 3;
    const bool fw = (s < 4);
    const int tid = threadIdx.x, lane = tid & 31, w = tid >> 5;

    __shared__ __half hC[64*SPAD], hH[64*SPAD];
    __shared__ float sCd[64];

    const float* base = xbc + (size_t)b*SEQLEN*CONVDIM;
    const int tau0 = k * CHUNK;

    for (int i = tid; i < 64*64; i += 128) {
        int t = i >> 6, n = i & 63;
        int orig = fw ? (tau0 + t) : (SEQLEN - 1 - (tau0 + t));
        hC[t*SPAD + n] = __float2half(base[(size_t)orig*CONVDIM + DINNER + DSTATE + n]);
        hH[t*SPAD + n] = __float2half(
            hp[((((size_t)s*NHEADSN + h)*NCH + k)*HEADDIM*DSTATE) + t*DSTATE + n]);  // t as p
    }
    if (tid < 64)
        sCd[tid] = cd[((size_t)s*NHEADSN + h)*SEQLEN + tau0 + tid];
    __syncthreads();

    const int arow = ((lane >> 3) & 1)*8 + (lane & 7);
    const int abyt = (lane >> 4) << 4;
    const int brow = (lane >> 4)*8 + (lane & 7);
    const int bbyt = ((lane >> 3) & 1) << 4;
    const uint32_t uC = (uint32_t)__cvta_generic_to_shared(hC);
    const uint32_t uH = (uint32_t)__cvta_generic_to_shared(hH);
    const uint32_t aoff = (uint32_t)((16*w + arow)*(SPAD*2) + abyt);

    float acc[8][4];
    #pragma unroll
    for (int j = 0; j < 8; j++) { acc[j][0]=acc[j][1]=acc[j][2]=acc[j][3]=0.f; }
    #pragma unroll
    for (int kk = 0; kk < 4; kk++) {
        const uint32_t ko = kk << 5;
        uint32_t af[4];
        ldsm4(af[0], af[1], af[2], af[3], uC + aoff + ko);
        #pragma unroll
        for (int j2 = 0; j2 < 4; j2++) {
            uint32_t q0, q1, q2, q3;
            ldsm4(q0, q1, q2, q3, uH + (uint32_t)((j2*16 + brow)*(SPAD*2) + bbyt) + ko);
            uint32_t b0[2]={q0,q1}, b1[2]={q2,q3};
            MMA16816(acc[j2*2], af, b0);
            MMA16816(acc[j2*2+1], af, b1);
        }
    }

    {
        const int g = lane >> 2, tg = lane & 3;
        const int t0 = 16*w + g;
        #pragma unroll
        for (int j = 0; j < 8; j++) {
            int col = 8*j + (tg << 1);
            #pragma unroll
            for (int r = 0; r < 2; r++) {
                int t = t0 + 8*r;
                int taug = tau0 + t;
                int to = fw ? (taug + 1) : (SEQLEN - 2 - taug);
                if (to >= 0 && to < SEQLEN) {
                    float cdt = sCd[t];
                    float* yp = &y[((size_t)s*SEQLEN + to)*DINNER + h*HEADDIM + col];
                    float2 old = *(float2*)yp;
                    old.x += cdt*acc[j][2*r];
                    old.y += cdt*acc[j][2*r+1];
                    *(float2*)yp = old;
                }
            }
        }
    }
}

// ---------------- gating + D skip + RMS norm (fp16 output) ----------------
__global__ void __launch_bounds__(256) gate_rms_kernel(
    const float* __restrict__ y, const float* __restrict__ xbc,
    const float* __restrict__ zx, const float* __restrict__ Dp,
    const float* __restrict__ rms_w, __half* __restrict__ out)
{
    int row = blockIdx.x;
    int b = row >> 11, t = row & 2047;
    int c = threadIdx.x << 2;
    size_t ybase = ((size_t)b*SEQLEN + t)*DINNER + c;
    const float4 yf = *(const float4*)&y[ybase];
    const float4 yb = *(const float4*)&y[ybase + (size_t)4*SEQLEN*DINNER];
    const float4 xo = *(const float4*)&xbc[((size_t)b*SEQLEN + t)*CONVDIM + c];
    const float4 zv = *(const float4*)&zx[((size_t)b*SEQLEN + t)*DINPROJ + c];
    float dp = Dp[c >> 6];
    float g0 = (yf.x + yb.x + xo.x*dp) * siluf(zv.x);
    float g1 = (yf.y + yb.y + xo.y*dp) * siluf(zv.y);
    float g2 = (yf.z + yb.z + xo.z*dp) * siluf(zv.z);
    float g3 = (yf.w + yb.w + xo.w*dp) * siluf(zv.w);
    float ss = g0*g0 + g1*g1 + g2*g2 + g3*g3;
    #pragma unroll
    for (int o = 16; o > 0; o >>= 1)
        ss += __shfl_xor_sync(0xffffffffu, ss, o);
    __shared__ float asum[8];
    int wid = threadIdx.x >> 5;
    if ((threadIdx.x & 31) == 0) asum[wid] = ss;
    __syncthreads();
    ss = asum[0]+asum[1]+asum[2]+asum[3]+asum[4]+asum[5]+asum[6]+asum[7];
    float scale = rsqrtf(ss * (1.0f/DINNER) + EPSV);
    const float4 wv = *(const float4*)&rms_w[c];
    __half2* op = (__half2*)(out + (size_t)row*DINNER + c);
    op[0] = __floats2half2_rn(g0*scale*wv.x, g1*scale*wv.y);
    op[1] = __floats2half2_rn(g2*scale*wv.z, g3*scale*wv.w);
}

// ---------------- launcher ----------------
extern "C" void kernel_launch(void* const* d_in, const int* in_sizes, int n_in,
                              void* d_out, int out_size)
{
    const float* x         = (const float*)d_in[0];
    const float* ln1_w     = (const float*)d_in[1];
    const float* ln1_b     = (const float*)d_in[2];
    const float* in_proj_w = (const float*)d_in[3];
    const float* conv_w    = (const float*)d_in[4];
    const float* conv_b    = (const float*)d_in[5];
    const float* dt_bias   = (const float*)d_in[6];
    const float* A_log     = (const float*)d_in[7];
    const float* Dp        = (const float*)d_in[8];
    const float* rms_w     = (const float*)d_in[9];
    const float* out_proj_w= (const float*)d_in[10];
    const float* ln2_w     = (const float*)d_in[11];
    const float* ln2_b     = (const float*)d_in[12];
    const float* fc1_w     = (const float*)d_in[13];
    const float* fc1_b     = (const float*)d_in[14];
    const float* fc2_w     = (const float*)d_in[15];
    const float* fc2_b     = (const float*)d_in[16];
    float* out = (float*)d_out;

    float *zx, *xbc, *ld, *dts, *y, *x2, *hf, *hp, *cdp;
    __half *h16, *yg16, *ff1h, *wip, *wop, *w1, *w2;
    cudaGetSymbolAddress((void**)&zx,  g_zx);
    cudaGetSymbolAddress((void**)&xbc, g_xbc);
    cudaGetSymbolAddress((void**)&ld,  g_ld);
    cudaGetSymbolAddress((void**)&dts, g_dts);
    cudaGetSymbolAddress((void**)&y,   g_y);
    cudaGetSymbolAddress((void**)&x2,  g_x2);
    cudaGetSymbolAddress((void**)&hf,  g_hf);
    cudaGetSymbolAddress((void**)&hp,  g_hp);
    cudaGetSymbolAddress((void**)&cdp, g_cd);
    cudaGetSymbolAddress((void**)&h16, g_h16);
    cudaGetSymbolAddress((void**)&yg16,g_yg16);
    cudaGetSymbolAddress((void**)&ff1h,g_ff1h);
    cudaGetSymbolAddress((void**)&wip, g_wip);
    cudaGetSymbolAddress((void**)&wop, g_wop);
    cudaGetSymbolAddress((void**)&w1,  g_w1);
    cudaGetSymbolAddress((void**)&w2,  g_w2);

    cudaFuncSetAttribute(gemm_h<0,0>, cudaFuncAttributeMaxDynamicSharedMemorySize, GEMM_SMEM);
    cudaFuncSetAttribute(gemm_h<1,1>, cudaFuncAttributeMaxDynamicSharedMemorySize, GEMM_SMEM);
    cudaFuncSetAttribute(gemm_h<2,0>, cudaFuncAttributeMaxDynamicSharedMemorySize, GEMM_SMEM);
    cudaFuncSetAttribute(gemm_h<3,0>, cudaFuncAttributeMaxDynamicSharedMemorySize, GEMM_SMEM);

    // 0. fused weight conversion
    {
        int n0 = DINPROJ*DMODEL, n1 = DMODEL*DINNER, n2 = DFF*DMODEL, n3 = DMODEL*DFF;
        int total4 = (n0+n1+n2+n3) >> 2;
        cvt_all_kernel<<<(total4 + 255)/256, 256>>>(
            in_proj_w, wip, n0, out_proj_w, wop, n1, fc1_w, w1, n2, fc2_w, w2, n3);
    }
    // 1. LN1
    ln_kernel<<<NROWS, 128>>>(x, ln1_w, ln1_b, h16);
    // 2. scan boundary zero
    zb_kernel<<<8, 256>>>(y);
    // 3. in_proj
    gemm_h<0,0><<<dim3((DINPROJ + 127)/128, NROWS/128), 512, GEMM_SMEM>>>(
        h16, wip, nullptr, nullptr, zx, NROWS, DINPROJ, DMODEL);
    // 4. dt preprocess (log decay)
    dt_kernel<<<(8*SEQLEN*NHEADSN)/256, 256>>>(zx, dt_bias, A_log, ld, dts);
    // 5. conv + silu
    conv_kernel<<<(NROWS*CONVDIM/4)/256, 256>>>(zx, conv_w, conv_b, xbc);
    // 6. SSD scan: per-chunk GEMMs (4096 blocks)
    scan_chunk<<<dim3(NHEADSN, 8, NCH), 128>>>(xbc, ld, dts, y, hf, cdp);
    // 7. SSD scan: serial combine (128 blocks)
    scan_combine<<<dim3(NHEADSN, 8), 256>>>(hf, cdp, hp);
    // 8. SSD scan: cross-chunk fixup (3968 blocks)
    scan_fix<<<dim3(NHEADSN, 8, NCH-1), 128>>>(xbc, cdp, hp, y);
    // 9. gate + D skip + RMS norm
    gate_rms_kernel<<<NROWS, 256>>>(y, xbc, zx, Dp, rms_w, yg16);
    // 10. out_proj + residual(x)
    gemm_h<2,0><<<dim3(DMODEL/128, NROWS/128), 512, GEMM_SMEM>>>(
        yg16, wop, nullptr, x, x2, NROWS, DMODEL, DINNER);
    // 11. LN2
    ln_kernel<<<NROWS, 128>>>(x2, ln2_w, ln2_b, h16);
    // 12. fc1 + bias + gelu
    gemm_h<1,1><<<dim3(DFF/128, NROWS/128), 512, GEMM_SMEM>>>(
        h16, w1, fc1_b, nullptr, ff1h, NROWS, DFF, DMODEL);
    // 13. fc2 + bias + residual(x2) -> d_out
    gemm_h<3,0><<<dim3(DMODEL/128, NROWS/128), 512, GEMM_SMEM>>>(
        ff1h, w2, fc2_b, x2, out, NROWS, DMODEL, DFF);
}

// round 16
// speedup vs baseline: 2.4943x; 1.0482x over previous
#include <cuda_runtime.h>
#include <cuda_fp16.h>
#include <math.h>
#include <stdint.h>

// ---------------- problem constants ----------------
#define BATCHN  4
#define SEQLEN  2048
#define DMODEL  512
#define DINNER  1024
#define NHEADSN 16
#define HEADDIM 64
#define DSTATE  64
#define CONVDIM 1152
#define DINPROJ 2208
#define DFF     2048
#define NROWS   (BATCHN*SEQLEN)   // 8192
#define EPSV    1e-5f
#define CHUNK   64
#define NCH     32
#define SPAD    72                // halves per smem row

// ---------------- scratch ----------------
__device__ float  g_zx  [NROWS*DINPROJ];
__device__ float  g_xbc [NROWS*CONVDIM];
__device__ float  g_ld  [8*SEQLEN*NHEADSN];
__device__ float  g_dts [8*SEQLEN*NHEADSN];
__device__ float  g_y   [8*SEQLEN*DINNER];
__device__ float  g_x2  [NROWS*DMODEL];
__device__ float  g_hf  [8*NHEADSN*NCH*HEADDIM*DSTATE];
__device__ float  g_hp  [8*NHEADSN*NCH*HEADDIM*DSTATE];
__device__ float  g_cd  [8*NHEADSN*SEQLEN];
__device__ __half g_h16 [NROWS*DMODEL];
__device__ __half g_yg16[NROWS*DINNER];
__device__ __half g_ff1h[NROWS*DFF];
__device__ __half g_wip [DINPROJ*DMODEL];
__device__ __half g_wop [DMODEL*DINNER];
__device__ __half g_w1  [DFF*DMODEL];
__device__ __half g_w2  [DMODEL*DFF];

// ---------------- helpers ----------------
__device__ __forceinline__ float geluf(float x) {
    return 0.5f * x * (1.0f + erff(x * 0.70710678118654752f));
}
__device__ __forceinline__ float siluf(float x) {
    return x / (1.0f + expf(-x));
}

#define CP16(dst, src) \
    asm volatile("cp.async.cg.shared.global [%0], [%1], 16;" :: "r"(dst), "l"(src))
#define CP16Z(dst, src, sz) \
    asm volatile("cp.async.cg.shared.global [%0], [%1], 16, %2;" :: "r"(dst), "l"(src), "r"(sz))
#define CP_COMMIT() asm volatile("cp.async.commit_group;")
#define CP_WAIT2()  asm volatile("cp.async.wait_group 2;")

__device__ __forceinline__ void ldsm4(uint32_t& q0, uint32_t& q1, uint32_t& q2, uint32_t& q3,
                                      uint32_t addr) {
    asm volatile("ldmatrix.sync.aligned.m8n8.x4.shared.b16 {%0,%1,%2,%3}, [%4];"
        : "=r"(q0), "=r"(q1), "=r"(q2), "=r"(q3) : "r"(addr));
}
#define MMA16816(c, a, b) \
    asm volatile("mma.sync.aligned.m16n8k16.row.col.f32.f16.f16.f32 " \
        "{%0,%1,%2,%3}, {%4,%5,%6,%7}, {%8,%9}, {%0,%1,%2,%3};" \
        : "+f"((c)[0]), "+f"((c)[1]), "+f"((c)[2]), "+f"((c)[3]) \
        : "r"((a)[0]), "r"((a)[1]), "r"((a)[2]), "r"((a)[3]), "r"((b)[0]), "r"((b)[1]))

// ---------------- fused f32 -> f16 weight convert ----------------
__global__ void cvt_all_kernel(
    const float* __restrict__ s0, __half* __restrict__ d0, int n0,
    const float* __restrict__ s1, __half* __restrict__ d1, int n1,
    const float* __restrict__ s2, __half* __restrict__ d2, int n2,
    const float* __restrict__ s3, __half* __restrict__ d3, int n3)
{
    int i = (blockIdx.x*blockDim.x + threadIdx.x) << 2;
    const float* s; __half* d;
    if (i < n0)                    { s = s0;      d = d0; }
    else if (i < n0+n1)            { s = s1 - n0; d = d1 - n0; }
    else if (i < n0+n1+n2)         { s = s2 - (n0+n1); d = d2 - (n0+n1); }
    else if (i < n0+n1+n2+n3)      { s = s3 - (n0+n1+n2); d = d3 - (n0+n1+n2); }
    else return;
    float4 v = *(const float4*)&s[i];
    *(__half2*)&d[i]   = __floats2half2_rn(v.x, v.y);
    *(__half2*)&d[i+2] = __floats2half2_rn(v.z, v.w);
}

// ---------------- scan boundary zero ----------------
__global__ void zb_kernel(float* __restrict__ y)
{
    int s = blockIdx.x;
    int t0 = (s < 4) ? 0 : (SEQLEN - 1);
    float4* p = (float4*)(y + ((size_t)s*SEQLEN + t0)*DINNER);
    p[threadIdx.x] = make_float4(0.f, 0.f, 0.f, 0.f);
}

// ---------------- LayerNorm (D=512), fp16 output ----------------
__global__ void __launch_bounds__(128) ln_kernel(
    const float* __restrict__ x, const float* __restrict__ w,
    const float* __restrict__ b, __half* __restrict__ out)
{
    int row = blockIdx.x;
    int tid = threadIdx.x;
    const float4 v = ((const float4*)(x + (size_t)row*DMODEL))[tid];
    float s  = v.x + v.y + v.z + v.w;
    float ss = v.x*v.x + v.y*v.y + v.z*v.z + v.w*v.w;
    #pragma unroll
    for (int o = 16; o > 0; o >>= 1) {
        s  += __shfl_xor_sync(0xffffffffu, s,  o);
        ss += __shfl_xor_sync(0xffffffffu, ss, o);
    }
    __shared__ float as[4], ass[4];
    int wid = tid >> 5;
    if ((tid & 31) == 0) { as[wid] = s; ass[wid] = ss; }
    __syncthreads();
    s  = as[0] + as[1] + as[2] + as[3];
    ss = ass[0] + ass[1] + ass[2] + ass[3];
    float mean = s * (1.0f/DMODEL);
    float var  = ss * (1.0f/DMODEL) - mean*mean;
    float rstd = rsqrtf(var + EPSV);
    const float4 wv = ((const float4*)w)[tid];
    const float4 bv = ((const float4*)b)[tid];
    float o0 = (v.x - mean)*rstd*wv.x + bv.x;
    float o1 = (v.y - mean)*rstd*wv.y + bv.y;
    float o2 = (v.z - mean)*rstd*wv.z + bv.z;
    float o3 = (v.w - mean)*rstd*wv.w + bv.w;
    __half2* op = (__half2*)(out + (size_t)row*DMODEL + (tid << 2));
    op[0] = __floats2half2_rn(o0, o1);
    op[1] = __floats2half2_rn(o2, o3);
}

// ---------------- fp16 tensor-core GEMM (f32 accum) ----------------
#define NSTAGE  4
#define ROWB    80
#define OPSTAGE (128*ROWB)
#define SMBOFF  (NSTAGE*OPSTAGE)
#define GEMM_SMEM (2*NSTAGE*OPSTAGE)

template<int EPI, int OUTH>
__global__ void __launch_bounds__(512) gemm_h(
    const __half* __restrict__ A, const __half* __restrict__ W,
    const float* __restrict__ bias, const float* __restrict__ res,
    void* __restrict__ Cout, int M, int N, int K)
{
    extern __shared__ char smem[];
    const uint32_t su = (uint32_t)__cvta_generic_to_shared(smem);
    const int tid = threadIdx.x, lane = tid & 31, wid = tid >> 5;
    const int bm = blockIdx.y << 7, bn = blockIdx.x << 7;
    const int wm = (wid & 3)  << 5;
    const int wn = (wid >> 2) << 5;
    const int ntiles = K >> 5;

    const int lrow = tid >> 2;
    const int lcp  = tid & 3;
    const int an = bn + lrow;
    const uint32_t bsz = (an < N) ? 16u : 0u;
    const __half* aSrc = A + (size_t)(bm + lrow)*K + (lcp << 3);
    const __half* bSrc = W + (size_t)((an < N) ? an : 0)*K + (lcp << 3);
    const uint32_t dA = su + lrow*ROWB + (lcp << 4);
    const uint32_t dB = dA + SMBOFF;

    const int arow = ((lane >> 3) & 1)*8 + (lane & 7);
    const int abyt = (lane >> 4) << 4;
    uint32_t abase[2];
    #pragma unroll
    for (int i = 0; i < 2; i++)
        abase[i] = su + (wm + i*16 + arow)*ROWB + abyt;
    const int brow = (lane >> 4)*8 + (lane & 7);
    const int bbyt = ((lane >> 3) & 1) << 4;
    uint32_t bbase[2];
    #pragma unroll
    for (int j2 = 0; j2 < 2; j2++)
        bbase[j2] = su + SMBOFF + (wn + j2*16 + brow)*ROWB + bbyt;

    float acc[8][4];
    #pragma unroll
    for (int i = 0; i < 8; i++) { acc[i][0]=acc[i][1]=acc[i][2]=acc[i][3]=0.f; }

    auto issue_tile = [&](int tf) {
        const uint32_t so = (tf & (NSTAGE-1))*OPSTAGE;
        const int kh = tf << 5;
        CP16 (dA + so, aSrc + kh);
        CP16Z(dB + so, bSrc + kh, bsz);
    };

    issue_tile(0); CP_COMMIT();
    issue_tile(1); CP_COMMIT();
    issue_tile(2); CP_COMMIT();

    for (int t = 0; t < ntiles; t++) {
        CP_WAIT2();
        __syncthreads();
        if (t + 3 < ntiles) issue_tile(t + 3);
        CP_COMMIT();

        const uint32_t so = (t & (NSTAGE-1))*OPSTAGE;
        #pragma unroll
        for (int ks = 0; ks < 2; ks++) {
            const uint32_t ko = ks << 5;
            uint32_t af[2][4], bf[4][2];
            #pragma unroll
            for (int i = 0; i < 2; i++)
                ldsm4(af[i][0], af[i][1], af[i][2], af[i][3], abase[i] + so + ko);
            #pragma unroll
            for (int j2 = 0; j2 < 2; j2++) {
                uint32_t q0, q1, q2, q3;
                ldsm4(q0, q1, q2, q3, bbase[j2] + so + ko);
                bf[j2*2  ][0] = q0; bf[j2*2  ][1] = q1;
                bf[j2*2+1][0] = q2; bf[j2*2+1][1] = q3;
            }
            #pragma unroll
            for (int i = 0; i < 2; i++)
                #pragma unroll
                for (int j = 0; j < 4; j++)
                    MMA16816(acc[i*4 + j], af[i], bf[j]);
        }
    }

    const int g = lane >> 2, tg = lane & 3;
    #pragma unroll
    for (int i = 0; i < 2; i++) {
        #pragma unroll
        for (int j = 0; j < 4; j++) {
            int row = bm + wm + i*16 + g;
            int col = bn + wn + j*8 + (tg << 1);
            if (col >= N) continue;
            float* c = acc[i*4 + j];
            float2 v0 = make_float2(c[0], c[1]);
            float2 v1 = make_float2(c[2], c[3]);
            if (EPI == 1 || EPI == 3) {
                float2 bv = *(const float2*)&bias[col];
                v0.x += bv.x; v0.y += bv.y;
                v1.x += bv.x; v1.y += bv.y;
            }
            if (EPI == 1) {
                v0.x = geluf(v0.x); v0.y = geluf(v0.y);
                v1.x = geluf(v1.x); v1.y = geluf(v1.y);
            }
            if (EPI == 2 || EPI == 3) {
                float2 r0 = *(const float2*)&res[(size_t)row*N + col];
                float2 r1 = *(const float2*)&res[(size_t)(row+8)*N + col];
                v0.x += r0.x; v0.y += r0.y;
                v1.x += r1.x; v1.y += r1.y;
            }
            if (OUTH) {
                __half* Ch = (__half*)Cout;
                *(__half2*)&Ch[(size_t)row*N + col]     = __floats2half2_rn(v0.x, v0.y);
                *(__half2*)&Ch[(size_t)(row+8)*N + col] = __floats2half2_rn(v1.x, v1.y);
            } else {
                float* Cf = (float*)Cout;
                *(float2*)&Cf[(size_t)row*N + col]     = v0;
                *(float2*)&Cf[(size_t)(row+8)*N + col] = v1;
            }
        }
    }
}

// ---------------- dt preprocess (log decay) ----------------
__global__ void dt_kernel(const float* __restrict__ zx, const float* __restrict__ dt_bias,
                          const float* __restrict__ A_log,
                          float* __restrict__ ldec, float* __restrict__ dts)
{
    int idx = blockIdx.x * blockDim.x + threadIdx.x;
    int hh = idx & 15;
    int t  = (idx >> 4) & (SEQLEN - 1);
    int s  = idx >> 15;
    int b  = s & 3;
    int off = (s < 4) ? 0 : NHEADSN;
    float raw = zx[((size_t)b*SEQLEN + t)*DINPROJ + (DINNER + CONVDIM) + off + hh] + dt_bias[hh];
    float sp = (raw > 20.f) ? raw : log1pf(expf(raw));
    float Ah = -expf(A_log[hh]);
    ldec[idx] = Ah * sp;
    dts[idx]  = sp;
}

// ---------------- depthwise causal conv7 + bias + silu (2 timesteps x 4 ch / thread) ----------------
__global__ void conv_kernel(const float* __restrict__ zx, const float* __restrict__ cw,
                            const float* __restrict__ cb, float* __restrict__ out)
{
    int idx = blockIdx.x * blockDim.x + threadIdx.x;   // over NROWS/2 * CONVDIM/4
    int c   = (idx % (CONVDIM/4)) << 2;
    int bt2 = idx / (CONVDIM/4);
    int t   = (bt2 & (SEQLEN/2 - 1)) << 1;
    int b   = bt2 >> 10;
    float4 bias4 = *(const float4*)&cb[c];
    float4 acc0 = bias4, acc1 = bias4;
    float w[4][7];
    #pragma unroll
    for (int k = 0; k < 4; k++)
        #pragma unroll
        for (int j = 0; j < 7; j++) w[k][j] = cw[(c+k)*7 + j];
    const float* base = zx + (size_t)b*SEQLEN*DINPROJ + DINNER + c;
    // rows t-6 .. t+1; row r contributes to acc0 with tap (r-(t-6)) and acc1 with tap (r-(t-5))
    #pragma unroll
    for (int r = 0; r < 8; r++) {
        int tt = t - 6 + r;
        if (tt < 0) continue;
        float4 v = *(const float4*)&base[(size_t)tt*DINPROJ];
        if (r < 7) {
            acc0.x = fmaf(v.x, w[0][r], acc0.x);
            acc0.y = fmaf(v.y, w[1][r], acc0.y);
            acc0.z = fmaf(v.z, w[2][r], acc0.z);
            acc0.w = fmaf(v.w, w[3][r], acc0.w);
        }
        if (r > 0) {
            acc1.x = fmaf(v.x, w[0][r-1], acc1.x);
            acc1.y = fmaf(v.y, w[1][r-1], acc1.y);
            acc1.z = fmaf(v.z, w[2][r-1], acc1.z);
            acc1.w = fmaf(v.w, w[3][r-1], acc1.w);
        }
    }
    size_t o0 = ((size_t)b*SEQLEN + t)*CONVDIM + c;
    float4 r0, r1;
    r0.x = siluf(acc0.x); r0.y = siluf(acc0.y); r0.z = siluf(acc0.z); r0.w = siluf(acc0.w);
    r1.x = siluf(acc1.x); r1.y = siluf(acc1.y); r1.z = siluf(acc1.z); r1.w = siluf(acc1.w);
    *(float4*)&out[o0] = r0;
    *(float4*)&out[o0 + CONVDIM] = r1;
}

// ---------------- SSD phase 1: chunk states only ----------------
// grid (16,8,32), 128 threads. H = Xw @ B -> hf; cd written.
__global__ void __launch_bounds__(128) scan_state(
    const float* __restrict__ xbc, const float* __restrict__ ldec,
    const float* __restrict__ dts, float* __restrict__ hf, float* __restrict__ cd)
{
    const int h = blockIdx.x, s = blockIdx.y, k = blockIdx.z;
    const int b = s & 3;
    const bool fw = (s < 4);
    const int tid = threadIdx.x, lane = tid & 31, w = tid >> 5;

    __shared__ __half hXt[64*SPAD], hBt[64*SPAD];
    __shared__ float sLd[64], sDt[64];

    const float* base = xbc + (size_t)b*SEQLEN*CONVDIM;
    const int tau0 = k * CHUNK;

    for (int i = tid; i < 64*64; i += 128) {
        int t = i >> 6, n = i & 63;
        int orig = fw ? (tau0 + t) : (SEQLEN - 1 - (tau0 + t));
        const float* row = base + (size_t)orig*CONVDIM;
        hBt[n*SPAD + t] = __float2half(row[DINNER + n]);
        hXt[n*SPAD + t] = __float2half(row[h*HEADDIM + n]);   // n as p
    }
    if (tid < 64) {
        int orig = fw ? (tau0 + tid) : (SEQLEN - 1 - (tau0 + tid));
        size_t di = ((size_t)s*SEQLEN + orig)*NHEADSN + h;
        float v = ldec[di];
        sDt[tid] = dts[di];
        #pragma unroll
        for (int d = 1; d < 32; d <<= 1) {
            float o = __shfl_up_sync(0xffffffffu, v, d);
            if (lane >= d) v += o;
        }
        sLd[tid] = v;
    }
    __syncthreads();
    if (tid >= 32 && tid < 64) sLd[tid] += sLd[31];
    __syncthreads();
    if (tid < 64)
        cd[((size_t)s*NHEADSN + h)*SEQLEN + tau0 + tid] = __expf(sLd[tid]);

    // weight Xt in place: Xw[p][t] = X[p][t] * exp(ld63 - ld_t) * dt_t
    {
        float ldl = sLd[63];
        for (int i = tid; i < 64*64; i += 128) {
            int p = i >> 6, t = i & 63;
            float wv = __expf(ldl - sLd[t]) * sDt[t];
            hXt[p*SPAD + t] = __float2half(__half2float(hXt[p*SPAD + t]) * wv);
        }
    }
    __syncthreads();

    const int arow = ((lane >> 3) & 1)*8 + (lane & 7);
    const int abyt = (lane >> 4) << 4;
    const int brow = (lane >> 4)*8 + (lane & 7);
    const int bbyt = ((lane >> 3) & 1) << 4;
    const uint32_t uXt = (uint32_t)__cvta_generic_to_shared(hXt);
    const uint32_t uBt = (uint32_t)__cvta_generic_to_shared(hBt);
    const uint32_t aoff = (uint32_t)((16*w + arow)*(SPAD*2) + abyt);

    float accH[8][4];
    #pragma unroll
    for (int j = 0; j < 8; j++) { accH[j][0]=accH[j][1]=accH[j][2]=accH[j][3]=0.f; }
    #pragma unroll
    for (int kk = 0; kk < 4; kk++) {
        const uint32_t ko = kk << 5;
        uint32_t af[4];
        ldsm4(af[0], af[1], af[2], af[3], uXt + aoff + ko);
        #pragma unroll
        for (int j2 = 0; j2 < 4; j2++) {
            uint32_t q0, q1, q2, q3;
            ldsm4(q0, q1, q2, q3, uBt + (uint32_t)((j2*16 + brow)*(SPAD*2) + bbyt) + ko);
            uint32_t b0[2]={q0,q1}, b1[2]={q2,q3};
            MMA16816(accH[j2*2], af, b0);
            MMA16816(accH[j2*2+1], af, b1);
        }
    }
    {
        const int g = lane >> 2, tg = lane & 3;
        const int r0 = 16*w + g;
        float* hfp = hf + ((((size_t)s*NHEADSN + h)*NCH + k)*HEADDIM*DSTATE);
        #pragma unroll
        for (int j = 0; j < 8; j++) {
            int col = 8*j + (tg << 1);
            #pragma unroll
            for (int r = 0; r < 2; r++) {
                int row = r0 + 8*r;
                *(float2*)&hfp[row*DSTATE + col] =
                    make_float2(accH[j][2*r], accH[j][2*r+1]);
            }
        }
    }
}

// ---------------- SSD phase 2: serial chunk-state combine ----------------
__global__ void __launch_bounds__(256) scan_combine(
    const float* __restrict__ hf, const float* __restrict__ cd,
    float* __restrict__ hp)
{
    const int h = blockIdx.x, s = blockIdx.y;
    const int off = threadIdx.x << 4;
    const size_t base = ((size_t)s*NHEADSN + h)*NCH*HEADDIM*DSTATE;
    const float* cdb = cd + ((size_t)s*NHEADSN + h)*SEQLEN;
    float prev[16];
    #pragma unroll
    for (int i = 0; i < 16; i++) prev[i] = 0.f;
    for (int k = 0; k < NCH; k++) {
        float4* dst = (float4*)(hp + base + (size_t)k*HEADDIM*DSTATE + off);
        #pragma unroll
        for (int v = 0; v < 4; v++)
            dst[v] = make_float4(prev[4*v], prev[4*v+1], prev[4*v+2], prev[4*v+3]);
        float P = cdb[k*CHUNK + CHUNK - 1];
        const float4* src = (const float4*)(hf + base + (size_t)k*HEADDIM*DSTATE + off);
        #pragma unroll
        for (int v = 0; v < 4; v++) {
            float4 hv = src[v];
            prev[4*v+0] = fmaf(prev[4*v+0], P, hv.x);
            prev[4*v+1] = fmaf(prev[4*v+1], P, hv.y);
            prev[4*v+2] = fmaf(prev[4*v+2], P, hv.z);
            prev[4*v+3] = fmaf(prev[4*v+3], P, hv.w);
        }
    }
}

// ---------------- SSD phase 3: full Y (local + prefix) in one pass ----------------
// grid (16,8,32), 128 threads. Y = mask(C B^T) X + diag(cd) C Hp^T -> y (single write).
__global__ void __launch_bounds__(128) scan_y(
    const float* __restrict__ xbc, const float* __restrict__ ldec,
    const float* __restrict__ dts, const float* __restrict__ hp,
    float* __restrict__ y)
{
    const int h = blockIdx.x, s = blockIdx.y, k = blockIdx.z;
    const int b = s & 3;
    const bool fw = (s < 4);
    const int tid = threadIdx.x, lane = tid & 31, w = tid >> 5;

    __shared__ __half hC[64*SPAD], hB[64*SPAD], hXt[64*SPAD], hHp[64*SPAD], hS[64*SPAD];
    __shared__ float sLd[64], sDt[64];

    const float* base = xbc + (size_t)b*SEQLEN*CONVDIM;
    const int tau0 = k * CHUNK;

    for (int i = tid; i < 64*64; i += 128) {
        int t = i >> 6, n = i & 63;
        int orig = fw ? (tau0 + t) : (SEQLEN - 1 - (tau0 + t));
        const float* row = base + (size_t)orig*CONVDIM;
        hB [t*SPAD + n] = __float2half(row[DINNER + n]);
        hC [t*SPAD + n] = __float2half(row[DINNER + DSTATE + n]);
        hXt[n*SPAD + t] = __float2half(row[h*HEADDIM + n]);   // n as p
        hHp[t*SPAD + n] = __float2half(
            hp[((((size_t)s*NHEADSN + h)*NCH + k)*HEADDIM*DSTATE) + t*DSTATE + n]); // t as p
    }
    if (tid < 64) {
        int orig = fw ? (tau0 + tid) : (SEQLEN - 1 - (tau0 + tid));
        size_t di = ((size_t)s*SEQLEN + orig)*NHEADSN + h;
        float v = ldec[di];
        sDt[tid] = dts[di];
        #pragma unroll
        for (int d = 1; d < 32; d <<= 1) {
            float o = __shfl_up_sync(0xffffffffu, v, d);
            if (lane >= d) v += o;
        }
        sLd[tid] = v;
    }
    __syncthreads();
    if (tid >= 32 && tid < 64) sLd[tid] += sLd[31];
    __syncthreads();

    const int arow = ((lane >> 3) & 1)*8 + (lane & 7);
    const int abyt = (lane >> 4) << 4;
    const int brow = (lane >> 4)*8 + (lane & 7);
    const int bbyt = ((lane >> 3) & 1) << 4;
    const uint32_t uC  = (uint32_t)__cvta_generic_to_shared(hC);
    const uint32_t uB  = (uint32_t)__cvta_generic_to_shared(hB);
    const uint32_t uXt = (uint32_t)__cvta_generic_to_shared(hXt);
    const uint32_t uHp = (uint32_t)__cvta_generic_to_shared(hHp);
    const uint32_t uS  = (uint32_t)__cvta_generic_to_shared(hS);
    const uint32_t aoff = (uint32_t)((16*w + arow)*(SPAD*2) + abyt);

    // k-loop 1: S = C @ B^T  and  Fix = C @ Hp^T (shared A fragments)
    float accS[8][4], accF[8][4];
    #pragma unroll
    for (int j = 0; j < 8; j++) {
        accS[j][0]=accS[j][1]=accS[j][2]=accS[j][3]=0.f;
        accF[j][0]=accF[j][1]=accF[j][2]=accF[j][3]=0.f;
    }
    #pragma unroll
    for (int kk = 0; kk < 4; kk++) {
        const uint32_t ko = kk << 5;
        uint32_t af[4];
        ldsm4(af[0], af[1], af[2], af[3], uC + aoff + ko);
        #pragma unroll
        for (int j2 = 0; j2 < 4; j2++) {
            const uint32_t bo = (uint32_t)((j2*16 + brow)*(SPAD*2) + bbyt) + ko;
            uint32_t q0, q1, q2, q3;
            ldsm4(q0, q1, q2, q3, uB + bo);
            { uint32_t b0[2]={q0,q1}, b1[2]={q2,q3};
              MMA16816(accS[j2*2], af, b0); MMA16816(accS[j2*2+1], af, b1); }
            ldsm4(q0, q1, q2, q3, uHp + bo);
            { uint32_t b0[2]={q0,q1}, b1[2]={q2,q3};
              MMA16816(accF[j2*2], af, b0); MMA16816(accF[j2*2+1], af, b1); }
        }
    }
    // mask + scale S -> hS
    {
        const int g = lane >> 2, tg = lane & 3;
        const int t0 = 16*w + g;
        #pragma unroll
        for (int j = 0; j < 8; j++) {
            int tc = 8*j + (tg << 1);
            float d0 = sDt[tc], d1 = sDt[tc+1];
            float l0 = sLd[tc], l1 = sLd[tc+1];
            #pragma unroll
            for (int r = 0; r < 2; r++) {
                int t = t0 + 8*r;
                float lt = sLd[t];
                float m0 = (tc     <= t) ? __expf(lt - l0)*d0 : 0.f;
                float m1 = (tc + 1 <= t) ? __expf(lt - l1)*d1 : 0.f;
                *(__half2*)&hS[t*SPAD + tc] =
                    __floats2half2_rn(accS[j][2*r]*m0, accS[j][2*r+1]*m1);
            }
        }
    }
    __syncthreads();

    // k-loop 2: Y = S' @ X
    float accY[8][4];
    #pragma unroll
    for (int j = 0; j < 8; j++) { accY[j][0]=accY[j][1]=accY[j][2]=accY[j][3]=0.f; }
    #pragma unroll
    for (int kk = 0; kk < 4; kk++) {
        const uint32_t ko = kk << 5;
        uint32_t af[4];
        ldsm4(af[0], af[1], af[2], af[3], uS + aoff + ko);
        #pragma unroll
        for (int j2 = 0; j2 < 4; j2++) {
            uint32_t q0, q1, q2, q3;
            ldsm4(q0, q1, q2, q3, uXt + (uint32_t)((j2*16 + brow)*(SPAD*2) + bbyt) + ko);
            uint32_t b0[2]={q0,q1}, b1[2]={q2,q3};
            MMA16816(accY[j2*2], af, b0);
            MMA16816(accY[j2*2+1], af, b1);
        }
    }

    // store: y = accY + cd_t * accF (single write)
    {
        const int g = lane >> 2, tg = lane & 3;
        const int t0 = 16*w + g;
        #pragma unroll
        for (int j = 0; j < 8; j++) {
            int col = 8*j + (tg << 1);
            #pragma unroll
            for (int r = 0; r < 2; r++) {
                int t = t0 + 8*r;
                int taug = tau0 + t;
                int to = fw ? (taug + 1) : (SEQLEN - 2 - taug);
                if (to >= 0 && to < SEQLEN) {
                    float cdt = __expf(sLd[t]);
                    float2 v;
                    v.x = accY[j][2*r]   + cdt*accF[j][2*r];
                    v.y = accY[j][2*r+1] + cdt*accF[j][2*r+1];
                    *(float2*)&y[((size_t)s*SEQLEN + to)*DINNER + h*HEADDIM + col] = v;
                }
            }
        }
    }
}

// ---------------- gating + D skip + RMS norm (fp16 output) ----------------
__global__ void __launch_bounds__(256) gate_rms_kernel(
    const float* __restrict__ y, const float* __restrict__ xbc,
    const float* __restrict__ zx, const float* __restrict__ Dp,
    const float* __restrict__ rms_w, __half* __restrict__ out)
{
    int row = blockIdx.x;
    int b = row >> 11, t = row & 2047;
    int c = threadIdx.x << 2;
    size_t ybase = ((size_t)b*SEQLEN + t)*DINNER + c;
    const float4 yf = *(const float4*)&y[ybase];
    const float4 yb = *(const float4*)&y[ybase + (size_t)4*SEQLEN*DINNER];
    const float4 xo = *(const float4*)&xbc[((size_t)b*SEQLEN + t)*CONVDIM + c];
    const float4 zv = *(const float4*)&zx[((size_t)b*SEQLEN + t)*DINPROJ + c];
    float dp = Dp[c >> 6];
    float g0 = (yf.x + yb.x + xo.x*dp) * siluf(zv.x);
    float g1 = (yf.y + yb.y + xo.y*dp) * siluf(zv.y);
    float g2 = (yf.z + yb.z + xo.z*dp) * siluf(zv.z);
    float g3 = (yf.w + yb.w + xo.w*dp) * siluf(zv.w);
    float ss = g0*g0 + g1*g1 + g2*g2 + g3*g3;
    #pragma unroll
    for (int o = 16; o > 0; o >>= 1)
        ss += __shfl_xor_sync(0xffffffffu, ss, o);
    __shared__ float asum[8];
    int wid = threadIdx.x >> 5;
    if ((threadIdx.x & 31) == 0) asum[wid] = ss;
    __syncthreads();
    ss = asum[0]+asum[1]+asum[2]+asum[3]+asum[4]+asum[5]+asum[6]+asum[7];
    float scale = rsqrtf(ss * (1.0f/DINNER) + EPSV);
    const float4 wv = *(const float4*)&rms_w[c];
    __half2* op = (__half2*)(out + (size_t)row*DINNER + c);
    op[0] = __floats2half2_rn(g0*scale*wv.x, g1*scale*wv.y);
    op[1] = __floats2half2_rn(g2*scale*wv.z, g3*scale*wv.w);
}

// ---------------- launcher ----------------
extern "C" void kernel_launch(void* const* d_in, const int* in_sizes, int n_in,
                              void* d_out, int out_size)
{
    const float* x         = (const float*)d_in[0];
    const float* ln1_w     = (const float*)d_in[1];
    const float* ln1_b     = (const float*)d_in[2];
    const float* in_proj_w = (const float*)d_in[3];
    const float* conv_w    = (const float*)d_in[4];
    const float* conv_b    = (const float*)d_in[5];
    const float* dt_bias   = (const float*)d_in[6];
    const float* A_log     = (const float*)d_in[7];
    const float* Dp        = (const float*)d_in[8];
    const float* rms_w     = (const float*)d_in[9];
    const float* out_proj_w= (const float*)d_in[10];
    const float* ln2_w     = (const float*)d_in[11];
    const float* ln2_b     = (const float*)d_in[12];
    const float* fc1_w     = (const float*)d_in[13];
    const float* fc1_b     = (const float*)d_in[14];
    const float* fc2_w     = (const float*)d_in[15];
    const float* fc2_b     = (const float*)d_in[16];
    float* out = (float*)d_out;

    float *zx, *xbc, *ld, *dts, *y, *x2, *hf, *hp, *cdp;
    __half *h16, *yg16, *ff1h, *wip, *wop, *w1, *w2;
    cudaGetSymbolAddress((void**)&zx,  g_zx);
    cudaGetSymbolAddress((void**)&xbc, g_xbc);
    cudaGetSymbolAddress((void**)&ld,  g_ld);
    cudaGetSymbolAddress((void**)&dts, g_dts);
    cudaGetSymbolAddress((void**)&y,   g_y);
    cudaGetSymbolAddress((void**)&x2,  g_x2);
    cudaGetSymbolAddress((void**)&hf,  g_hf);
    cudaGetSymbolAddress((void**)&hp,  g_hp);
    cudaGetSymbolAddress((void**)&cdp, g_cd);
    cudaGetSymbolAddress((void**)&h16, g_h16);
    cudaGetSymbolAddress((void**)&yg16,g_yg16);
    cudaGetSymbolAddress((void**)&ff1h,g_ff1h);
    cudaGetSymbolAddress((void**)&wip, g_wip);
    cudaGetSymbolAddress((void**)&wop, g_wop);
    cudaGetSymbolAddress((void**)&w1,  g_w1);
    cudaGetSymbolAddress((void**)&w2,  g_w2);

    cudaFuncSetAttribute(gemm_h<0,0>, cudaFuncAttributeMaxDynamicSharedMemorySize, GEMM_SMEM);
    cudaFuncSetAttribute(gemm_h<1,1>, cudaFuncAttributeMaxDynamicSharedMemorySize, GEMM_SMEM);
    cudaFuncSetAttribute(gemm_h<2,0>, cudaFuncAttributeMaxDynamicSharedMemorySize, GEMM_SMEM);
    cudaFuncSetAttribute(gemm_h<3,0>, cudaFuncAttributeMaxDynamicSharedMemorySize, GEMM_SMEM);

    // 0. fused weight conversion
    {
        int n0 = DINPROJ*DMODEL, n1 = DMODEL*DINNER, n2 = DFF*DMODEL, n3 = DMODEL*DFF;
        int total4 = (n0+n1+n2+n3) >> 2;
        cvt_all_kernel<<<(total4 + 255)/256, 256>>>(
            in_proj_w, wip, n0, out_proj_w, wop, n1, fc1_w, w1, n2, fc2_w, w2, n3);
    }
    // 1. LN1
    ln_kernel<<<NROWS, 128>>>(x, ln1_w, ln1_b, h16);
    // 2. scan boundary zero
    zb_kernel<<<8, 256>>>(y);
    // 3. in_proj (launch #4 — profiled)
    gemm_h<0,0><<<dim3((DINPROJ + 127)/128, NROWS/128), 512, GEMM_SMEM>>>(
        h16, wip, nullptr, nullptr, zx, NROWS, DINPROJ, DMODEL);
    // 4. dt preprocess
    dt_kernel<<<(8*SEQLEN*NHEADSN)/256, 256>>>(zx, dt_bias, A_log, ld, dts);
    // 5. conv + silu (2 timesteps/thread)
    conv_kernel<<<(NROWS*CONVDIM/8)/256, 256>>>(zx, conv_w, conv_b, xbc);
    // 6. SSD: chunk states (4096 blocks)
    scan_state<<<dim3(NHEADSN, 8, NCH), 128>>>(xbc, ld, dts, hf, cdp);
    // 7. SSD: serial combine (128 blocks)
    scan_combine<<<dim3(NHEADSN, 8), 256>>>(hf, cdp, hp);
    // 8. SSD: full Y (4096 blocks, single y write)
    scan_y<<<dim3(NHEADSN, 8, NCH), 128>>>(xbc, ld, dts, hp, y);
    // 9. gate + D skip + RMS norm
    gate_rms_kernel<<<NROWS, 256>>>(y, xbc, zx, Dp, rms_w, yg16);
    // 10. out_proj + residual(x)
    gemm_h<2,0><<<dim3(DMODEL/128, NROWS/128), 512, GEMM_SMEM>>>(
        yg16, wop, nullptr, x, x2, NROWS, DMODEL, DINNER);
    // 11. LN2
    ln_kernel<<<NROWS, 128>>>(x2, ln2_w, ln2_b, h16);
    // 12. fc1 + bias + gelu
    gemm_h<1,1><<<dim3(DFF/128, NROWS/128), 512, GEMM_SMEM>>>(
        h16, w1, fc1_b, nullptr, ff1h, NROWS, DFF, DMODEL);
    // 13. fc2 + bias + residual(x2) -> d_out
    gemm_h<3,0><<<dim3(DMODEL/128, NROWS/128), 512, GEMM_SMEM>>>(
        ff1h, w2, fc2_b, x2, out, NROWS, DMODEL, DFF);
}